// round 3
// baseline (speedup 1.0000x reference)
#include <cuda_runtime.h>
#include <math.h>

#define Bb 64
#define Ss 256
#define BS (Bb*Ss)
#define DL 300
#define DA 74
#define DV 35
#define DH 128

__device__ float g_seq[3u*BS*DH];
__device__ float g_xg_gru[6u*BS*192];
__device__ float g_x[3u*BS*DH];
__device__ float g_tstep[(unsigned)BS*384];
__device__ float g_sc[(unsigned)Bb*Ss*Ss];
__device__ float g_xg_lstm[2u*BS*512];
__device__ float g_sf[(unsigned)BS*256];
__device__ float g_xg_rgn[2u*BS*384];
__device__ float g_rgn_out[2u*Bb*128];

#define BM 128
#define BN 64
#define BK 16

// C[z] = A[z] @ W[z] (+bias) (+=C). A:[M,K] ld=K, W:[K,N] ld=N, C ld=ldc.
template<bool GATHER, bool ACC>
__launch_bounds__(256)
__global__ void gemm_nn(const float* __restrict__ A, const float* __restrict__ W,
                        const float* __restrict__ bias, float* __restrict__ C,
                        int M, int N, int K, long sA, long sW, long sC, int ldc,
                        const int* __restrict__ gidx)
{
    __shared__ alignas(16) float As[BK][BM+4];
    __shared__ alignas(16) float Bs[BK][BN+4];
    int z = blockIdx.z;
    const float* Ab = A + (long)z*sA;
    const float* Wb = W + (long)z*sW;
    float* Cb = C + (long)z*sC;
    int m0 = blockIdx.y*BM, n0 = blockIdx.x*BN;
    int tid = threadIdx.x, tx = tid&15, ty = tid>>4;
    float acc[8][4];
#pragma unroll
    for (int i=0;i<8;i++)
#pragma unroll
        for (int j=0;j<4;j++) acc[i][j]=0.f;
    int arow = tid>>1, acol = (tid&1)*8;
    long gr = m0 + arow;
    const float* arow_ptr = Ab + (GATHER ? (long)gidx[gr] : gr) * (long)K;
    int brow = tid>>4, bcol = (tid&15)*4;
    bool kv4 = ((K&3)==0);
    for (int k0=0; k0<K; k0+=BK) {
#pragma unroll
        for (int h=0; h<2; h++) {
            int c = acol + h*4;
            float4 av;
            if (kv4 && (k0+c+3 < K)) av = *(const float4*)(arow_ptr+k0+c);
            else {
                av.x = (k0+c+0<K)?arow_ptr[k0+c+0]:0.f;
                av.y = (k0+c+1<K)?arow_ptr[k0+c+1]:0.f;
                av.z = (k0+c+2<K)?arow_ptr[k0+c+2]:0.f;
                av.w = (k0+c+3<K)?arow_ptr[k0+c+3]:0.f;
            }
            As[c+0][arow]=av.x; As[c+1][arow]=av.y;
            As[c+2][arow]=av.z; As[c+3][arow]=av.w;
        }
        {
            float4 bv = make_float4(0.f,0.f,0.f,0.f);
            if (k0+brow < K) bv = *(const float4*)(Wb + (long)(k0+brow)*N + n0 + bcol);
            *(float4*)&Bs[brow][bcol] = bv;
        }
        __syncthreads();
#pragma unroll
        for (int kk=0; kk<BK; kk++) {
            float4 a0 = *(const float4*)&As[kk][ty*8];
            float4 a1 = *(const float4*)&As[kk][ty*8+4];
            float4 b  = *(const float4*)&Bs[kk][tx*4];
            float ar[8]={a0.x,a0.y,a0.z,a0.w,a1.x,a1.y,a1.z,a1.w};
            float br[4]={b.x,b.y,b.z,b.w};
#pragma unroll
            for (int i=0;i<8;i++)
#pragma unroll
                for (int j=0;j<4;j++) acc[i][j] += ar[i]*br[j];
        }
        __syncthreads();
    }
    float bv[4]={0.f,0.f,0.f,0.f};
    if (bias) {
#pragma unroll
        for (int j=0;j<4;j++) bv[j]=bias[n0+tx*4+j];
    }
#pragma unroll
    for (int i=0;i<8;i++) {
        float* cp = Cb + (long)(m0+ty*8+i)*ldc + n0 + tx*4;
        float4 o;
        o.x=acc[i][0]+bv[0]; o.y=acc[i][1]+bv[1];
        o.z=acc[i][2]+bv[2]; o.w=acc[i][3]+bv[3];
        if (ACC) { float4 od=*(const float4*)cp; o.x+=od.x;o.y+=od.y;o.z+=od.z;o.w+=od.w; }
        *(float4*)cp = o;
    }
}

// C[z][i][j] = scale * sum_k A[z][i][k]*B[z][j][k].  K multiple of 16.
__launch_bounds__(256)
__global__ void gemm_nt_scaled(const float* __restrict__ A, const float* __restrict__ B,
                               float* __restrict__ C, int M, int N, int K,
                               long sA, long sB, long sC, float scale)
{
    __shared__ alignas(16) float As[BK][BM+4];
    __shared__ alignas(16) float Bs[BK][BN+4];
    int z = blockIdx.z;
    const float* Ab = A + (long)z*sA;
    const float* Bp = B + (long)z*sB;
    float* Cb = C + (long)z*sC;
    int m0 = blockIdx.y*BM, n0 = blockIdx.x*BN;
    int tid = threadIdx.x, tx = tid&15, ty = tid>>4;
    float acc[8][4];
#pragma unroll
    for (int i=0;i<8;i++)
#pragma unroll
        for (int j=0;j<4;j++) acc[i][j]=0.f;
    int arow = tid>>1, acol = (tid&1)*8;
    const float* arow_ptr = Ab + (long)(m0+arow)*K;
    int bjj = tid>>2, bkc = (tid&3)*4;
    const float* brow_ptr = Bp + (long)(n0+bjj)*K;
    for (int k0=0; k0<K; k0+=BK) {
#pragma unroll
        for (int h=0; h<2; h++) {
            int c = acol + h*4;
            float4 av = *(const float4*)(arow_ptr+k0+c);
            As[c+0][arow]=av.x; As[c+1][arow]=av.y;
            As[c+2][arow]=av.z; As[c+3][arow]=av.w;
        }
        {
            float4 bv = *(const float4*)(brow_ptr+k0+bkc);
            Bs[bkc+0][bjj]=bv.x; Bs[bkc+1][bjj]=bv.y;
            Bs[bkc+2][bjj]=bv.z; Bs[bkc+3][bjj]=bv.w;
        }
        __syncthreads();
#pragma unroll
        for (int kk=0; kk<BK; kk++) {
            float4 a0 = *(const float4*)&As[kk][ty*8];
            float4 a1 = *(const float4*)&As[kk][ty*8+4];
            float4 b  = *(const float4*)&Bs[kk][tx*4];
            float ar[8]={a0.x,a0.y,a0.z,a0.w,a1.x,a1.y,a1.z,a1.w};
            float br[4]={b.x,b.y,b.z,b.w};
#pragma unroll
            for (int i=0;i<8;i++)
#pragma unroll
                for (int j=0;j<4;j++) acc[i][j] += ar[i]*br[j];
        }
        __syncthreads();
    }
#pragma unroll
    for (int i=0;i<8;i++) {
        float* cp = Cb + (long)(m0+ty*8+i)*N + n0 + tx*4;
        float4 o;
        o.x=acc[i][0]*scale; o.y=acc[i][1]*scale;
        o.z=acc[i][2]*scale; o.w=acc[i][3]*scale;
        *(float4*)cp = o;
    }
}

__launch_bounds__(256)
__global__ void softmax256(float* __restrict__ sc)
{
    long row = blockIdx.x;
    int t = threadIdx.x;
    float v = sc[row*256+t];
    float m = v;
#pragma unroll
    for (int o=16;o;o>>=1) m = fmaxf(m, __shfl_xor_sync(0xffffffffu, m, o));
    __shared__ float wred[8];
    if ((t&31)==0) wred[t>>5]=m;
    __syncthreads();
    float bm = wred[0];
#pragma unroll
    for (int i=1;i<8;i++) bm = fmaxf(bm, wred[i]);
    float p = expf(v-bm);
    float s = p;
#pragma unroll
    for (int o=16;o;o>>=1) s += __shfl_xor_sync(0xffffffffu, s, o);
    __syncthreads();
    if ((t&31)==0) wred[t>>5]=s;
    __syncthreads();
    float bs = 0.f;
#pragma unroll
    for (int i=0;i<8;i++) bs += wred[i];
    sc[row*256+t] = p/bs;
}

// biGRU: grid 3*2*64 (m,d,b), 192 thr. Wh column register-resident.
__launch_bounds__(192)
__global__ void gru_rec(const float* __restrict__ xg_all, const float* __restrict__ Wh,
                        const float* __restrict__ bh, float* __restrict__ x_out,
                        float* __restrict__ tstep)
{
    int bx = blockIdx.x;
    int m = bx>>7, d = (bx>>6)&1, b = bx&63, md = m*2+d;
    int j = threadIdx.x;
    float wreg[64];
#pragma unroll
    for (int k=0;k<64;k++) wreg[k] = Wh[((long)md*64+k)*192 + j];
    float bhj = bh[md*192 + j];
    __shared__ alignas(16) float h_s[64];
    __shared__ float pre_s[192], xn_s[64];
    if (j<64) h_s[j]=0.f;
    const float* xg = xg_all + ((long)md*BS + (long)b*Ss)*192;
    for (int t=0;t<Ss;t++) {
        int s = d ? (Ss-1-t) : t;
        __syncthreads();
        float acc = bhj;
        const float4* h4p = (const float4*)h_s;
#pragma unroll
        for (int q=0;q<16;q++) {
            float4 h4 = h4p[q];
            acc += h4.x*wreg[4*q] + h4.y*wreg[4*q+1] + h4.z*wreg[4*q+2] + h4.w*wreg[4*q+3];
        }
        float xgv = xg[(long)s*192 + j];
        if (j<128) pre_s[j] = acc + xgv;
        else { pre_s[j] = acc; xn_s[j-128] = xgv; }
        __syncthreads();
        if (j<64) {
            float r = 1.f/(1.f+expf(-pre_s[j]));
            float zg = 1.f/(1.f+expf(-pre_s[64+j]));
            float n = tanhf(xn_s[j] + r*pre_s[128+j]);
            float hn = (1.f-zg)*n + zg*h_s[j];
            h_s[j] = hn;
            long row = (long)b*Ss + s;
            x_out[((long)m*BS + row)*128 + d*64 + j] = hn;
            tstep[row*384 + m*128 + d*64 + j] = hn;
        }
    }
}

// biLSTM: grid 2*64 (d,b), 512 thr. Wh rows 0..63 regs, 64..127 smem.
__launch_bounds__(512, 1)
__global__ void lstm_rec(const float* __restrict__ xg_all, const float* __restrict__ Wh,
                         const float* __restrict__ bh, float* __restrict__ sf)
{
    extern __shared__ float sm[];
    float* Wlo = sm;                 // [64][512]
    float* h_s = sm + 64*512;        // [128]
    float* pre_s = h_s + 128;        // [512]
    int bx = blockIdx.x, d = bx>>6, b = bx&63;
    int j = threadIdx.x;
    const float* Whd = Wh + (long)d*128*512;
    float wreg[64];
#pragma unroll
    for (int k=0;k<64;k++) wreg[k] = Whd[(long)k*512 + j];
    for (int r=0;r<64;r++) Wlo[r*512 + j] = Whd[(long)(64+r)*512 + j];
    float bhj = bh[d*512 + j];
    float c = 0.f;
    if (j<128) h_s[j]=0.f;
    const float* xg = xg_all + ((long)d*BS + (long)b*Ss)*512;
    for (int t=0;t<Ss;t++) {
        int s = d ? (Ss-1-t) : t;
        __syncthreads();
        float acc = bhj;
        const float4* h4p = (const float4*)h_s;
#pragma unroll
        for (int q=0;q<16;q++) {
            float4 h4 = h4p[q];
            acc += h4.x*wreg[4*q] + h4.y*wreg[4*q+1] + h4.z*wreg[4*q+2] + h4.w*wreg[4*q+3];
        }
#pragma unroll
        for (int q=0;q<16;q++) {
            float4 h4 = h4p[16+q];
            acc += h4.x*Wlo[(4*q+0)*512+j] + h4.y*Wlo[(4*q+1)*512+j]
                 + h4.z*Wlo[(4*q+2)*512+j] + h4.w*Wlo[(4*q+3)*512+j];
        }
        acc += xg[(long)s*512 + j];
        pre_s[j] = acc;
        __syncthreads();
        if (j<128) {
            float ig = pre_s[j], fg = pre_s[128+j], gg = pre_s[256+j], og = pre_s[384+j];
            c = 1.f/(1.f+expf(-fg))*c + 1.f/(1.f+expf(-ig))*tanhf(gg);
            float h = 1.f/(1.f+expf(-og))*tanhf(c);
            h_s[j] = h;
            sf[((long)b*Ss + s)*256 + d*128 + j] = h;
        }
    }
}

// RGN: grid 2*64 (k,b), 384 thr. Returns final state.
__launch_bounds__(384, 1)
__global__ void rgn_rec(const float* __restrict__ xg_all, const float* __restrict__ Wh,
                        const float* __restrict__ state0, const float* __restrict__ state1,
                        float* __restrict__ outbuf)
{
    extern __shared__ float sm[];
    float* Wlo = sm;                 // [64][384]
    float* h_s = sm + 64*384;        // [128]
    float* pre_s = h_s + 128;        // [384]
    float* xn_s = pre_s + 384;       // [128]
    int bx = blockIdx.x, kk = bx>>6, b = bx&63;
    int j = threadIdx.x;
    const float* Whd = Wh + (long)kk*128*384;
    float wreg[64];
#pragma unroll
    for (int k=0;k<64;k++) wreg[k] = Whd[(long)k*384 + j];
    for (int r=0;r<64;r++) Wlo[r*384 + j] = Whd[(long)(64+r)*384 + j];
    if (j<128) h_s[j] = (kk==0?state0:state1)[b*128 + j];
    const float* xg = xg_all + ((long)kk*BS + (long)b*Ss)*384;
    for (int t=0;t<Ss;t++) {
        int s = kk ? (Ss-1-t) : t;
        __syncthreads();
        float acc = 0.f;
        const float4* h4p = (const float4*)h_s;
#pragma unroll
        for (int q=0;q<16;q++) {
            float4 h4 = h4p[q];
            acc += h4.x*wreg[4*q] + h4.y*wreg[4*q+1] + h4.z*wreg[4*q+2] + h4.w*wreg[4*q+3];
        }
#pragma unroll
        for (int q=0;q<16;q++) {
            float4 h4 = h4p[16+q];
            acc += h4.x*Wlo[(4*q+0)*384+j] + h4.y*Wlo[(4*q+1)*384+j]
                 + h4.z*Wlo[(4*q+2)*384+j] + h4.w*Wlo[(4*q+3)*384+j];
        }
        float xgv = xg[(long)s*384 + j];
        if (j<256) pre_s[j] = acc + xgv;
        else { pre_s[j] = acc; xn_s[j-256] = xgv; }
        __syncthreads();
        if (j<128) {
            float r = 1.f/(1.f+expf(-pre_s[j]));
            float z = 1.f/(1.f+expf(-pre_s[128+j]));
            float n = tanhf(xn_s[j] + r*pre_s[256+j]);
            h_s[j] = (1.f-z)*n + z*h_s[j];
        }
    }
    __syncthreads();
    if (j<128) outbuf[((long)kk*64 + b)*128 + j] = h_s[j];
}

__launch_bounds__(32)
__global__ void final_fc(const float* __restrict__ outbuf,
                         const float* __restrict__ fc1W, const float* __restrict__ fc1b,
                         const float* __restrict__ fc2W, const float* __restrict__ fc2b,
                         float* __restrict__ out)
{
    int b = blockIdx.x, t = threadIdx.x;
    float acc = fc1b[t];
    for (int k=0;k<128;k++) {
        float x = outbuf[b*128+k] + outbuf[64*128 + b*128 + k];
        acc += x * fc1W[k*32 + t];
    }
    float h = acc > 0.f ? acc : 0.01f*acc;
    float v = h * fc2W[t];
#pragma unroll
    for (int o=16;o;o>>=1) v += __shfl_xor_sync(0xffffffffu, v, o);
    if (t==0) out[b] = v + fc2b[0];
}

extern "C" void kernel_launch(void* const* d_in, const int* in_sizes, int n_in,
                              void* d_out, int out_size)
{
    (void)in_sizes; (void)n_in; (void)out_size;
    const int*   sentences = (const int*)  d_in[0];
    const float* acoustic  = (const float*)d_in[1];
    const float* video     = (const float*)d_in[2];
    const float* state0    = (const float*)d_in[3];
    const float* state1    = (const float*)d_in[4];
    const float* emb       = (const float*)d_in[5];
    const float* proj_l_W  = (const float*)d_in[6];
    const float* proj_l_b  = (const float*)d_in[7];
    const float* proj_a_W  = (const float*)d_in[8];
    const float* proj_a_b  = (const float*)d_in[9];
    const float* proj_v_W  = (const float*)d_in[10];
    const float* proj_v_b  = (const float*)d_in[11];
    const float* gru_Wi    = (const float*)d_in[12];
    const float* gru_Wh    = (const float*)d_in[13];
    const float* gru_bi    = (const float*)d_in[14];
    const float* gru_bh    = (const float*)d_in[15];
    const float* lstm_Wi   = (const float*)d_in[16];
    const float* lstm_Wh   = (const float*)d_in[17];
    const float* lstm_bi   = (const float*)d_in[18];
    const float* lstm_bh   = (const float*)d_in[19];
    const float* rgn_Wx    = (const float*)d_in[20];
    const float* rgn_Wh    = (const float*)d_in[21];
    const float* rgn_b     = (const float*)d_in[22];
    const float* fc1_W     = (const float*)d_in[23];
    const float* fc1_b     = (const float*)d_in[24];
    const float* fc2_W     = (const float*)d_in[25];
    const float* fc2_b     = (const float*)d_in[26];
    float* out = (float*)d_out;

    float *seq,*xg_gru,*x,*tstep,*sc,*xg_lstm,*sf,*xg_rgn,*rgn_out;
    cudaGetSymbolAddress((void**)&seq, g_seq);
    cudaGetSymbolAddress((void**)&xg_gru, g_xg_gru);
    cudaGetSymbolAddress((void**)&x, g_x);
    cudaGetSymbolAddress((void**)&tstep, g_tstep);
    cudaGetSymbolAddress((void**)&sc, g_sc);
    cudaGetSymbolAddress((void**)&xg_lstm, g_xg_lstm);
    cudaGetSymbolAddress((void**)&sf, g_sf);
    cudaGetSymbolAddress((void**)&xg_rgn, g_xg_rgn);
    cudaGetSymbolAddress((void**)&rgn_out, g_rgn_out);

    cudaFuncSetAttribute(lstm_rec, cudaFuncAttributeMaxDynamicSharedMemorySize, 134*1024);
    cudaFuncSetAttribute(rgn_rec,  cudaFuncAttributeMaxDynamicSharedMemorySize, 102*1024);

    // modality projections
    gemm_nn<true,false><<<dim3(DH/BN, BS/BM, 1), 256>>>(
        emb, proj_l_W, proj_l_b, seq, BS, DH, DL, 0,0,0, DH, sentences);
    gemm_nn<false,false><<<dim3(DH/BN, BS/BM, 1), 256>>>(
        acoustic, proj_a_W, proj_a_b, seq + 1l*BS*DH, BS, DH, DA, 0,0,0, DH, nullptr);
    gemm_nn<false,false><<<dim3(DH/BN, BS/BM, 1), 256>>>(
        video, proj_v_W, proj_v_b, seq + 2l*BS*DH, BS, DH, DV, 0,0,0, DH, nullptr);

    // GRU input projections (6)
    for (int m=0;m<3;m++)
        for (int d=0;d<2;d++) {
            int md = m*2+d;
            gemm_nn<false,false><<<dim3(192/BN, BS/BM, 1), 256>>>(
                seq + (long)m*BS*DH, gru_Wi + (long)md*DH*192, gru_bi + (long)md*192,
                xg_gru + (long)md*BS*192, BS, 192, DH, 0,0,0, 192, nullptr);
        }

    // biGRU recurrences (also initializes tstep slabs)
    gru_rec<<<3*2*64, 192>>>(xg_gru, gru_Wh, gru_bh, x, tstep);

    // JCAF cross-attentions: tstep[:, q*128:] += softmax(q@kv^T * scale) @ kv
    const float scale = 0.08838834764831845f; // 1/sqrt(128)
    const int pairs[6][2] = {{0,1},{0,2},{1,0},{1,2},{2,0},{2,1}};
    for (int p=0;p<6;p++) {
        int q = pairs[p][0], kv = pairs[p][1];
        gemm_nt_scaled<<<dim3(Ss/BN, Ss/BM, Bb), 256>>>(
            x + (long)q*BS*128, x + (long)kv*BS*128, sc,
            Ss, Ss, 128, (long)Ss*128, (long)Ss*128, (long)Ss*Ss, scale);
        softmax256<<<Bb*Ss, 256>>>(sc);
        gemm_nn<false,true><<<dim3(128/BN, Ss/BM, Bb), 256>>>(
            sc, x + (long)kv*BS*128, nullptr, tstep + (long)q*128,
            Ss, 128, Ss, (long)Ss*Ss, (long)Ss*128, (long)Ss*384, 384, nullptr);
    }

    // LSTM input projections (2)
    for (int d=0;d<2;d++)
        gemm_nn<false,false><<<dim3(512/BN, BS/BM, 1), 256>>>(
            tstep, lstm_Wi + (long)d*384*512, lstm_bi + (long)d*512,
            xg_lstm + (long)d*BS*512, BS, 512, 384, 0,0,0, 512, nullptr);

    // biLSTM recurrence
    lstm_rec<<<2*64, 512, 134*1024>>>(xg_lstm, lstm_Wh, lstm_bh, sf);

    // RGN input projections (2)
    for (int k=0;k<2;k++)
        gemm_nn<false,false><<<dim3(384/BN, BS/BM, 1), 256>>>(
            sf, rgn_Wx + (long)k*256*384, rgn_b + (long)k*384,
            xg_rgn + (long)k*BS*384, BS, 384, 256, 0,0,0, 384, nullptr);

    // RGN recurrences
    rgn_rec<<<2*64, 384, 102*1024>>>(xg_rgn, rgn_Wh, state0, state1, rgn_out);

    // final FC
    final_fc<<<Bb, 32>>>(rgn_out, fc1_W, fc1_b, fc2_W, fc2_b, out);
}

// round 4
// speedup vs baseline: 1.2997x; 1.2997x over previous
#include <cuda_runtime.h>
#include <math.h>
#include <stdint.h>

#define Bb 64
#define Ss 256
#define BS (Bb*Ss)
#define DL 300
#define DA 74
#define DV 35
#define DH 128

__device__ float g_seq[3u*BS*DH];
__device__ float g_xg_gru[6u*BS*192];
__device__ float g_x[3u*BS*DH];
__device__ float g_tstep[(unsigned)BS*384];
__device__ float g_sc[(unsigned)Bb*Ss*Ss];
__device__ float g_xg_lstm[2u*BS*512];
__device__ float g_sf[(unsigned)BS*256];
__device__ float g_xg_rgn[2u*BS*384];
__device__ float g_rgn_out[2u*Bb*128];

// ---------------------------------------------------------------------------
// TF32 tensor-core GEMM.
//   C[z] = scale * (A[z] @ op(B[z])) (+bias) (+=C)
//   A: [M,K] row-major (optionally gathered rows via gidx)
//   B: NN -> [K,N] row-major;  TRANSB -> [N,K] row-major (C = A @ B^T)
// Block tile 128x128, BK=32, 256 threads (8 warps, warp tile 64x32),
// mma.sync.m16n8k8.tf32. Conflict-free smem:
//   As[m][k]  stride 36  (reads: bank = 4g+tig, unique)
//   Bs[k][n]  stride 136 (NN reads: bank = 8tig+g, unique)
//   Bs[n][k]  stride 36  (TRANSB reads: bank = 4g+tig, unique)
// ---------------------------------------------------------------------------
#define ASTR 36
#define BSTR 136

__device__ __forceinline__ uint32_t f2tf32(float f) {
    uint32_t u;
    asm("cvt.rna.tf32.f32 %0, %1;" : "=r"(u) : "f"(f));
    return u;
}

__device__ __forceinline__ void mma_tf32(float c[4], const uint32_t a[4], const uint32_t b[2]) {
    asm volatile(
        "mma.sync.aligned.m16n8k8.row.col.f32.tf32.tf32.f32 "
        "{%0,%1,%2,%3}, {%4,%5,%6,%7}, {%8,%9}, {%0,%1,%2,%3};"
        : "+f"(c[0]), "+f"(c[1]), "+f"(c[2]), "+f"(c[3])
        : "r"(a[0]), "r"(a[1]), "r"(a[2]), "r"(a[3]), "r"(b[0]), "r"(b[1]));
}

template<bool GATHER, bool TRANSB, bool ACC>
__launch_bounds__(256, 2)
__global__ void gemm_tc(const float* __restrict__ A, const float* __restrict__ B,
                        const float* __restrict__ bias, float* __restrict__ C,
                        int M, int N, int K, long sA, long sB, long sC, int ldc,
                        float scale, const int* __restrict__ gidx)
{
    __shared__ uint32_t As_[128*ASTR];
    __shared__ uint32_t Bs_[128*ASTR];   // covers both 32*BSTR (4352) and 128*36 (4608)

    int z = blockIdx.z;
    const float* Ab = A + (long)z*sA;
    const float* Bp = B + (long)z*sB;
    float* Cb = C + (long)z*sC;
    int m0 = blockIdx.y*128, n0 = blockIdx.x*128;
    int tid = threadIdx.x;
    int warp = tid>>5, lane = tid&31;
    int g = lane>>2, tig = lane&3;
    int wm = (warp&1)*64, wn = (warp>>1)*32;

    float c[4][4][4];
#pragma unroll
    for (int mt=0;mt<4;mt++)
#pragma unroll
        for (int nt=0;nt<4;nt++)
#pragma unroll
            for (int i=0;i<4;i++) c[mt][nt][i]=0.f;

    bool k4 = ((K&3)==0);
    int ktn = (K+31)>>5;

    for (int kt=0; kt<ktn; kt++) {
        int k0 = kt*32;
        // ---- load A tile: 128 rows x 32 k ----
#pragma unroll
        for (int p=0;p<4;p++) {
            int idx = tid + p*256;
            int row = idx>>3, kq = (idx&7)*4;
            long grow = m0 + row;
            const float* ap = Ab + (GATHER ? (long)gidx[grow] : grow)*(long)K + k0 + kq;
            float4 v = make_float4(0.f,0.f,0.f,0.f);
            if (k4) {
                if (k0+kq+3 < K) v = *(const float4*)ap;
            } else {
                if (k0+kq+0 < K) v.x = ap[0];
                if (k0+kq+1 < K) v.y = ap[1];
                if (k0+kq+2 < K) v.z = ap[2];
                if (k0+kq+3 < K) v.w = ap[3];
            }
            uint4 u;
            u.x=f2tf32(v.x); u.y=f2tf32(v.y); u.z=f2tf32(v.z); u.w=f2tf32(v.w);
            *(uint4*)&As_[row*ASTR + kq] = u;
        }
        // ---- load B tile ----
        if (TRANSB) {
            // B: [N,K]; Bs[n][k] stride 36
#pragma unroll
            for (int p=0;p<4;p++) {
                int idx = tid + p*256;
                int row = idx>>3, kq = (idx&7)*4;
                float4 v = make_float4(0.f,0.f,0.f,0.f);
                if (n0+row < N) {
                    const float* bp = Bp + (long)(n0+row)*K + k0 + kq;
                    if (k4) {
                        if (k0+kq+3 < K) v = *(const float4*)bp;
                    } else {
                        if (k0+kq+0 < K) v.x = bp[0];
                        if (k0+kq+1 < K) v.y = bp[1];
                        if (k0+kq+2 < K) v.z = bp[2];
                        if (k0+kq+3 < K) v.w = bp[3];
                    }
                }
                uint4 u;
                u.x=f2tf32(v.x); u.y=f2tf32(v.y); u.z=f2tf32(v.z); u.w=f2tf32(v.w);
                *(uint4*)&Bs_[row*ASTR + kq] = u;
            }
        } else {
            // B: [K,N]; Bs[k][n] stride 136
#pragma unroll
            for (int p=0;p<4;p++) {
                int idx = tid + p*256;
                int k = idx>>5, n4 = (idx&31)*4;
                float4 v = make_float4(0.f,0.f,0.f,0.f);
                if (k0+k < K) {
                    const float* bp = Bp + (long)(k0+k)*N + n0 + n4;
                    if (n0+n4+3 < N) v = *(const float4*)bp;
                    else {
                        if (n0+n4+0 < N) v.x = bp[0];
                        if (n0+n4+1 < N) v.y = bp[1];
                        if (n0+n4+2 < N) v.z = bp[2];
                    }
                }
                uint4 u;
                u.x=f2tf32(v.x); u.y=f2tf32(v.y); u.z=f2tf32(v.z); u.w=f2tf32(v.w);
                *(uint4*)&Bs_[k*BSTR + n4] = u;
            }
        }
        __syncthreads();
        // ---- compute: 4 k-steps of k8 ----
#pragma unroll
        for (int ks=0;ks<4;ks++) {
            uint32_t a[4][4], b[4][2];
#pragma unroll
            for (int mt=0;mt<4;mt++) {
                int base = (wm + mt*16 + g)*ASTR + ks*8 + tig;
                a[mt][0] = As_[base];
                a[mt][1] = As_[base + 8*ASTR];
                a[mt][2] = As_[base + 4];
                a[mt][3] = As_[base + 8*ASTR + 4];
            }
#pragma unroll
            for (int nt=0;nt<4;nt++) {
                if (TRANSB) {
                    int base = (wn + nt*8 + g)*ASTR + ks*8 + tig;
                    b[nt][0] = Bs_[base];
                    b[nt][1] = Bs_[base + 4];
                } else {
                    int base = (ks*8 + tig)*BSTR + wn + nt*8 + g;
                    b[nt][0] = Bs_[base];
                    b[nt][1] = Bs_[base + 4*BSTR];
                }
            }
#pragma unroll
            for (int mt=0;mt<4;mt++)
#pragma unroll
                for (int nt=0;nt<4;nt++)
                    mma_tf32(c[mt][nt], a[mt], b[nt]);
        }
        __syncthreads();
    }

    // ---- epilogue ----
#pragma unroll
    for (int mt=0;mt<4;mt++) {
        long m = m0 + wm + mt*16 + g;
#pragma unroll
        for (int nt=0;nt<4;nt++) {
            int n = n0 + wn + nt*8 + tig*2;
            if (n < N) {
                float bx=0.f, by=0.f;
                if (bias) { bx = bias[n]; by = bias[n+1]; }
                float* p0 = Cb + m*ldc + n;
                float* p1 = p0 + 8l*ldc;
                float2 v0, v1;
                v0.x = c[mt][nt][0]*scale + bx;
                v0.y = c[mt][nt][1]*scale + by;
                v1.x = c[mt][nt][2]*scale + bx;
                v1.y = c[mt][nt][3]*scale + by;
                if (ACC) {
                    float2 o0 = *(const float2*)p0, o1 = *(const float2*)p1;
                    v0.x+=o0.x; v0.y+=o0.y; v1.x+=o1.x; v1.y+=o1.y;
                }
                *(float2*)p0 = v0;
                *(float2*)p1 = v1;
            }
        }
    }
}

// ---------------------------------------------------------------------------
__launch_bounds__(256)
__global__ void softmax256(float* __restrict__ sc)
{
    long row = blockIdx.x;
    int t = threadIdx.x;
    float v = sc[row*256+t];
    float m = v;
#pragma unroll
    for (int o=16;o;o>>=1) m = fmaxf(m, __shfl_xor_sync(0xffffffffu, m, o));
    __shared__ float wred[8];
    if ((t&31)==0) wred[t>>5]=m;
    __syncthreads();
    float bm = wred[0];
#pragma unroll
    for (int i=1;i<8;i++) bm = fmaxf(bm, wred[i]);
    float p = expf(v-bm);
    float s = p;
#pragma unroll
    for (int o=16;o;o>>=1) s += __shfl_xor_sync(0xffffffffu, s, o);
    __syncthreads();
    if ((t&31)==0) wred[t>>5]=s;
    __syncthreads();
    float bs = 0.f;
#pragma unroll
    for (int i=0;i<8;i++) bs += wred[i];
    sc[row*256+t] = p/bs;
}

// biGRU: grid 3*2*64 (m,d,b), 192 thr. Wh column register-resident.
__launch_bounds__(192)
__global__ void gru_rec(const float* __restrict__ xg_all, const float* __restrict__ Wh,
                        const float* __restrict__ bh, float* __restrict__ x_out,
                        float* __restrict__ tstep)
{
    int bx = blockIdx.x;
    int m = bx>>7, d = (bx>>6)&1, b = bx&63, md = m*2+d;
    int j = threadIdx.x;
    float wreg[64];
#pragma unroll
    for (int k=0;k<64;k++) wreg[k] = Wh[((long)md*64+k)*192 + j];
    float bhj = bh[md*192 + j];
    __shared__ alignas(16) float h_s[64];
    __shared__ float pre_s[192], xn_s[64];
    if (j<64) h_s[j]=0.f;
    const float* xg = xg_all + ((long)md*BS + (long)b*Ss)*192;
    for (int t=0;t<Ss;t++) {
        int s = d ? (Ss-1-t) : t;
        __syncthreads();
        float acc = bhj;
        const float4* h4p = (const float4*)h_s;
#pragma unroll
        for (int q=0;q<16;q++) {
            float4 h4 = h4p[q];
            acc += h4.x*wreg[4*q] + h4.y*wreg[4*q+1] + h4.z*wreg[4*q+2] + h4.w*wreg[4*q+3];
        }
        float xgv = xg[(long)s*192 + j];
        if (j<128) pre_s[j] = acc + xgv;
        else { pre_s[j] = acc; xn_s[j-128] = xgv; }
        __syncthreads();
        if (j<64) {
            float r = 1.f/(1.f+expf(-pre_s[j]));
            float zg = 1.f/(1.f+expf(-pre_s[64+j]));
            float n = tanhf(xn_s[j] + r*pre_s[128+j]);
            float hn = (1.f-zg)*n + zg*h_s[j];
            h_s[j] = hn;
            long row = (long)b*Ss + s;
            x_out[((long)m*BS + row)*128 + d*64 + j] = hn;
            tstep[row*384 + m*128 + d*64 + j] = hn;
        }
    }
}

// biLSTM: grid 2*64 (d,b), 512 thr.
__launch_bounds__(512, 1)
__global__ void lstm_rec(const float* __restrict__ xg_all, const float* __restrict__ Wh,
                         const float* __restrict__ bh, float* __restrict__ sf)
{
    extern __shared__ float sm[];
    float* Wlo = sm;
    float* h_s = sm + 64*512;
    float* pre_s = h_s + 128;
    int bx = blockIdx.x, d = bx>>6, b = bx&63;
    int j = threadIdx.x;
    const float* Whd = Wh + (long)d*128*512;
    float wreg[64];
#pragma unroll
    for (int k=0;k<64;k++) wreg[k] = Whd[(long)k*512 + j];
    for (int r=0;r<64;r++) Wlo[r*512 + j] = Whd[(long)(64+r)*512 + j];
    float bhj = bh[d*512 + j];
    float c = 0.f;
    if (j<128) h_s[j]=0.f;
    const float* xg = xg_all + ((long)d*BS + (long)b*Ss)*512;
    for (int t=0;t<Ss;t++) {
        int s = d ? (Ss-1-t) : t;
        __syncthreads();
        float acc = bhj;
        const float4* h4p = (const float4*)h_s;
#pragma unroll
        for (int q=0;q<16;q++) {
            float4 h4 = h4p[q];
            acc += h4.x*wreg[4*q] + h4.y*wreg[4*q+1] + h4.z*wreg[4*q+2] + h4.w*wreg[4*q+3];
        }
#pragma unroll
        for (int q=0;q<16;q++) {
            float4 h4 = h4p[16+q];
            acc += h4.x*Wlo[(4*q+0)*512+j] + h4.y*Wlo[(4*q+1)*512+j]
                 + h4.z*Wlo[(4*q+2)*512+j] + h4.w*Wlo[(4*q+3)*512+j];
        }
        acc += xg[(long)s*512 + j];
        pre_s[j] = acc;
        __syncthreads();
        if (j<128) {
            float ig = pre_s[j], fg = pre_s[128+j], gg = pre_s[256+j], og = pre_s[384+j];
            c = 1.f/(1.f+expf(-fg))*c + 1.f/(1.f+expf(-ig))*tanhf(gg);
            float h = 1.f/(1.f+expf(-og))*tanhf(c);
            h_s[j] = h;
            sf[((long)b*Ss + s)*256 + d*128 + j] = h;
        }
    }
}

// RGN: grid 2*64 (k,b), 384 thr.
__launch_bounds__(384, 1)
__global__ void rgn_rec(const float* __restrict__ xg_all, const float* __restrict__ Wh,
                        const float* __restrict__ state0, const float* __restrict__ state1,
                        float* __restrict__ outbuf)
{
    extern __shared__ float sm[];
    float* Wlo = sm;
    float* h_s = sm + 64*384;
    float* pre_s = h_s + 128;
    float* xn_s = pre_s + 384;
    int bx = blockIdx.x, kk = bx>>6, b = bx&63;
    int j = threadIdx.x;
    const float* Whd = Wh + (long)kk*128*384;
    float wreg[64];
#pragma unroll
    for (int k=0;k<64;k++) wreg[k] = Whd[(long)k*384 + j];
    for (int r=0;r<64;r++) Wlo[r*384 + j] = Whd[(long)(64+r)*384 + j];
    if (j<128) h_s[j] = (kk==0?state0:state1)[b*128 + j];
    const float* xg = xg_all + ((long)kk*BS + (long)b*Ss)*384;
    for (int t=0;t<Ss;t++) {
        int s = kk ? (Ss-1-t) : t;
        __syncthreads();
        float acc = 0.f;
        const float4* h4p = (const float4*)h_s;
#pragma unroll
        for (int q=0;q<16;q++) {
            float4 h4 = h4p[q];
            acc += h4.x*wreg[4*q] + h4.y*wreg[4*q+1] + h4.z*wreg[4*q+2] + h4.w*wreg[4*q+3];
        }
#pragma unroll
        for (int q=0;q<16;q++) {
            float4 h4 = h4p[16+q];
            acc += h4.x*Wlo[(4*q+0)*384+j] + h4.y*Wlo[(4*q+1)*384+j]
                 + h4.z*Wlo[(4*q+2)*384+j] + h4.w*Wlo[(4*q+3)*384+j];
        }
        float xgv = xg[(long)s*384 + j];
        if (j<256) pre_s[j] = acc + xgv;
        else { pre_s[j] = acc; xn_s[j-256] = xgv; }
        __syncthreads();
        if (j<128) {
            float r = 1.f/(1.f+expf(-pre_s[j]));
            float z = 1.f/(1.f+expf(-pre_s[128+j]));
            float n = tanhf(xn_s[j] + r*pre_s[256+j]);
            h_s[j] = (1.f-z)*n + z*h_s[j];
        }
    }
    __syncthreads();
    if (j<128) outbuf[((long)kk*64 + b)*128 + j] = h_s[j];
}

__launch_bounds__(32)
__global__ void final_fc(const float* __restrict__ outbuf,
                         const float* __restrict__ fc1W, const float* __restrict__ fc1b,
                         const float* __restrict__ fc2W, const float* __restrict__ fc2b,
                         float* __restrict__ out)
{
    int b = blockIdx.x, t = threadIdx.x;
    float acc = fc1b[t];
    for (int k=0;k<128;k++) {
        float x = outbuf[b*128+k] + outbuf[64*128 + b*128 + k];
        acc += x * fc1W[k*32 + t];
    }
    float h = acc > 0.f ? acc : 0.01f*acc;
    float v = h * fc2W[t];
#pragma unroll
    for (int o=16;o;o>>=1) v += __shfl_xor_sync(0xffffffffu, v, o);
    if (t==0) out[b] = v + fc2b[0];
}

extern "C" void kernel_launch(void* const* d_in, const int* in_sizes, int n_in,
                              void* d_out, int out_size)
{
    (void)in_sizes; (void)n_in; (void)out_size;
    const int*   sentences = (const int*)  d_in[0];
    const float* acoustic  = (const float*)d_in[1];
    const float* video     = (const float*)d_in[2];
    const float* state0    = (const float*)d_in[3];
    const float* state1    = (const float*)d_in[4];
    const float* emb       = (const float*)d_in[5];
    const float* proj_l_W  = (const float*)d_in[6];
    const float* proj_l_b  = (const float*)d_in[7];
    const float* proj_a_W  = (const float*)d_in[8];
    const float* proj_a_b  = (const float*)d_in[9];
    const float* proj_v_W  = (const float*)d_in[10];
    const float* proj_v_b  = (const float*)d_in[11];
    const float* gru_Wi    = (const float*)d_in[12];
    const float* gru_Wh    = (const float*)d_in[13];
    const float* gru_bi    = (const float*)d_in[14];
    const float* gru_bh    = (const float*)d_in[15];
    const float* lstm_Wi   = (const float*)d_in[16];
    const float* lstm_Wh   = (const float*)d_in[17];
    const float* lstm_bi   = (const float*)d_in[18];
    const float* lstm_bh   = (const float*)d_in[19];
    const float* rgn_Wx    = (const float*)d_in[20];
    const float* rgn_Wh    = (const float*)d_in[21];
    const float* rgn_b     = (const float*)d_in[22];
    const float* fc1_W     = (const float*)d_in[23];
    const float* fc1_b     = (const float*)d_in[24];
    const float* fc2_W     = (const float*)d_in[25];
    const float* fc2_b     = (const float*)d_in[26];
    float* out = (float*)d_out;

    float *seq,*xg_gru,*x,*tstep,*sc,*xg_lstm,*sf,*xg_rgn,*rgn_out;
    cudaGetSymbolAddress((void**)&seq, g_seq);
    cudaGetSymbolAddress((void**)&xg_gru, g_xg_gru);
    cudaGetSymbolAddress((void**)&x, g_x);
    cudaGetSymbolAddress((void**)&tstep, g_tstep);
    cudaGetSymbolAddress((void**)&sc, g_sc);
    cudaGetSymbolAddress((void**)&xg_lstm, g_xg_lstm);
    cudaGetSymbolAddress((void**)&sf, g_sf);
    cudaGetSymbolAddress((void**)&xg_rgn, g_xg_rgn);
    cudaGetSymbolAddress((void**)&rgn_out, g_rgn_out);

    cudaFuncSetAttribute(lstm_rec, cudaFuncAttributeMaxDynamicSharedMemorySize, 134*1024);
    cudaFuncSetAttribute(rgn_rec,  cudaFuncAttributeMaxDynamicSharedMemorySize, 102*1024);

    // modality projections (tf32 MMA)
    gemm_tc<true,false,false><<<dim3(1, BS/128, 1), 256>>>(
        emb, proj_l_W, proj_l_b, seq, BS, DH, DL, 0,0,0, DH, 1.f, sentences);
    gemm_tc<false,false,false><<<dim3(1, BS/128, 1), 256>>>(
        acoustic, proj_a_W, proj_a_b, seq + 1l*BS*DH, BS, DH, DA, 0,0,0, DH, 1.f, nullptr);
    gemm_tc<false,false,false><<<dim3(1, BS/128, 1), 256>>>(
        video, proj_v_W, proj_v_b, seq + 2l*BS*DH, BS, DH, DV, 0,0,0, DH, 1.f, nullptr);

    // GRU input projections (6)
    for (int m=0;m<3;m++)
        for (int d=0;d<2;d++) {
            int md = m*2+d;
            gemm_tc<false,false,false><<<dim3(2, BS/128, 1), 256>>>(
                seq + (long)m*BS*DH, gru_Wi + (long)md*DH*192, gru_bi + (long)md*192,
                xg_gru + (long)md*BS*192, BS, 192, DH, 0,0,0, 192, 1.f, nullptr);
        }

    // biGRU recurrences (also initializes tstep slabs)
    gru_rec<<<3*2*64, 192>>>(xg_gru, gru_Wh, gru_bh, x, tstep);

    // JCAF cross-attentions: tstep[:, q*128:] += softmax(q@kv^T * scale) @ kv
    const float scale = 0.08838834764831845f; // 1/sqrt(128)
    const int pairs[6][2] = {{0,1},{0,2},{1,0},{1,2},{2,0},{2,1}};
    for (int p=0;p<6;p++) {
        int q = pairs[p][0], kv = pairs[p][1];
        gemm_tc<false,true,false><<<dim3(2, 2, Bb), 256>>>(
            x + (long)q*BS*128, x + (long)kv*BS*128, nullptr, sc,
            Ss, Ss, 128, (long)Ss*128, (long)Ss*128, (long)Ss*Ss, Ss, scale, nullptr);
        softmax256<<<Bb*Ss, 256>>>(sc);
        gemm_tc<false,false,true><<<dim3(1, 2, Bb), 256>>>(
            sc, x + (long)kv*BS*128, nullptr, tstep + (long)q*128,
            Ss, 128, Ss, (long)Ss*Ss, (long)Ss*128, (long)Ss*384, 384, 1.f, nullptr);
    }

    // LSTM input projections (2)
    for (int d=0;d<2;d++)
        gemm_tc<false,false,false><<<dim3(4, BS/128, 1), 256>>>(
            tstep, lstm_Wi + (long)d*384*512, lstm_bi + (long)d*512,
            xg_lstm + (long)d*BS*512, BS, 512, 384, 0,0,0, 512, 1.f, nullptr);

    // biLSTM recurrence
    lstm_rec<<<2*64, 512, 134*1024>>>(xg_lstm, lstm_Wh, lstm_bh, sf);

    // RGN input projections (2)
    for (int k=0;k<2;k++)
        gemm_tc<false,false,false><<<dim3(3, BS/128, 1), 256>>>(
            sf, rgn_Wx + (long)k*256*384, rgn_b + (long)k*384,
            xg_rgn + (long)k*BS*384, BS, 384, 256, 0,0,0, 384, 1.f, nullptr);

    // RGN recurrences
    rgn_rec<<<2*64, 384, 102*1024>>>(xg_rgn, rgn_Wh, state0, state1, rgn_out);

    // final FC
    final_fc<<<Bb, 32>>>(rgn_out, fc1_W, fc1_b, fc2_W, fc2_b, out);
}

// round 5
// speedup vs baseline: 1.5917x; 1.2246x over previous
#include <cuda_runtime.h>
#include <math.h>
#include <stdint.h>

#define Bb 64
#define Ss 256
#define BS (Bb*Ss)
#define DL 300
#define DA 74
#define DV 35
#define DH 128

__device__ float g_seq[3u*BS*DH];
__device__ float g_xg_gru[6u*BS*192];
__device__ float g_x[3u*BS*DH];
__device__ float g_tstep[(unsigned)BS*384];
__device__ float g_sc[6u*(unsigned)Bb*Ss*Ss];     // [pair][b][256][256]
__device__ float g_xg_lstm[2u*BS*512];
__device__ float g_sf[(unsigned)BS*256];
__device__ float g_xg_rgn[2u*BS*384];
__device__ float g_rgn_out[2u*Bb*128];

// ---------------------------------------------------------------------------
// TF32 tensor-core GEMM, cp.async 2-stage pipelined, z-batched.
// Block tile 128x128, BK=32, 256 thr (8 warps, warp tile 64x32),
// mma.sync.m16n8k8.tf32 on raw f32 bits (HW truncation to tf32).
// smem (dynamic): [As0][Bs0][As1][Bs1], each 128*36 words (72 KB total).
// MODE 0: Ab=A+z*sA, Bb=B+z*sB, bias+z*sBias, Cb=C+z*sC
// MODE 1: GRU — Ab=A+(z>>1)*sA, rest as MODE 0
// MODE 2: QK  — p=z>>6, b=z&63: A=x[q(p)] slab, B=x[kv(p)] slab, C=sc[z]
// MODE 3: PV  — pp=z>>6, b=z&63, p=2*pp+aux: A=sc[p*64+b], B=x[kv(p)], C=tstep[q(p) slab] (+=)
// ---------------------------------------------------------------------------
#define ASTR 36
#define BSTR 136
#define AWORDS (128*ASTR)

__device__ __forceinline__ uint32_t s2u(const void* p) {
    return (uint32_t)__cvta_generic_to_shared(p);
}
__device__ __forceinline__ void cpa16(uint32_t dst, const void* src, int bytes) {
    asm volatile("cp.async.cg.shared.global [%0], [%1], 16, %2;"
                 :: "r"(dst), "l"(src), "r"(bytes));
}
__device__ __forceinline__ void mma_tf32(float c[4], const uint32_t a[4], const uint32_t b[2]) {
    asm volatile(
        "mma.sync.aligned.m16n8k8.row.col.f32.tf32.tf32.f32 "
        "{%0,%1,%2,%3}, {%4,%5,%6,%7}, {%8,%9}, {%0,%1,%2,%3};"
        : "+f"(c[0]), "+f"(c[1]), "+f"(c[2]), "+f"(c[3])
        : "r"(a[0]), "r"(a[1]), "r"(a[2]), "r"(a[3]), "r"(b[0]), "r"(b[1]));
}

template<int MODE, bool TRANSB, bool ACC, bool PIPE, bool GATHER>
__launch_bounds__(256, 2)
__global__ void gemm_tc(const float* __restrict__ A, const float* __restrict__ B,
                        const float* __restrict__ bias, float* __restrict__ C,
                        int M, int N, int K,
                        long sA, long sB, long sBias, long sC, int ldc,
                        float scale, const int* __restrict__ gidx, int aux)
{
    extern __shared__ uint32_t smp[];
    uint32_t* AsB[2] = { smp, smp + 2*AWORDS };
    uint32_t* BsB[2] = { smp + AWORDS, smp + 3*AWORDS };

    const int qtab[6]  = {0,0,1,1,2,2};
    const int kvtab[6] = {1,2,0,2,0,1};

    int z = blockIdx.z;
    const float *Ab, *Bp, *bp = nullptr;
    float* Cb;
    if (MODE == 0 || MODE == 1) {
        Ab = A + (MODE==1 ? (long)(z>>1)*sA : (long)z*sA);
        Bp = B + (long)z*sB;
        bp = bias ? bias + (long)z*sBias : nullptr;
        Cb = C + (long)z*sC;
    } else if (MODE == 2) {
        int p = z>>6, b = z&63;
        Ab = A + ((long)qtab[p]*BS + (long)b*Ss)*128;
        Bp = B + ((long)kvtab[p]*BS + (long)b*Ss)*128;
        Cb = C + (long)z*Ss*Ss;
    } else { // MODE 3
        int pp = z>>6, b = z&63;
        int p = 2*pp + aux;
        Ab = A + ((long)p*64 + b)*(long)Ss*Ss;
        Bp = B + ((long)kvtab[p]*BS + (long)b*Ss)*128;
        Cb = C + (long)qtab[p]*128 + (long)b*Ss*384;
    }

    int m0 = blockIdx.y*128, n0 = blockIdx.x*128;
    int tid = threadIdx.x;
    int warp = tid>>5, lane = tid&31;
    int g = lane>>2, tig = lane&3;
    int wm = (warp&1)*64, wn = (warp>>1)*32;

    float c[4][4][4];
#pragma unroll
    for (int mt=0;mt<4;mt++)
#pragma unroll
        for (int nt=0;nt<4;nt++)
#pragma unroll
            for (int i=0;i<4;i++) c[mt][nt][i]=0.f;

    // cached row pointers
    int lrow = tid>>3;            // 0..31
    int akq  = (tid&7)*4;         // 0..28
    const float* arp[4];
#pragma unroll
    for (int p=0;p<4;p++) {
        long grow = m0 + lrow + p*32;
        long r = GATHER ? (long)gidx[grow] : grow;
        arp[p] = Ab + r*(long)K;
    }
    const float* brp[4];
    if (TRANSB) {
#pragma unroll
        for (int p=0;p<4;p++) brp[p] = Bp + (long)(n0 + lrow + p*32)*K;
    }
    int bnk = tid>>5;             // 0..7 (NN B k within group)
    int bn4 = (tid&31)*4;

    auto load_tile = [&](uint32_t* As, uint32_t* Bs, int k0) {
        if (PIPE) {
#pragma unroll
            for (int p=0;p<4;p++) {
                int gk = k0 + akq;
                int bytes = (K - gk)*4; bytes = bytes<0?0:(bytes>16?16:bytes);
                const float* src = bytes ? (arp[p] + gk) : Ab;
                cpa16(s2u(&As[(lrow + p*32)*ASTR + akq]), src, bytes);
            }
            if (TRANSB) {
#pragma unroll
                for (int p=0;p<4;p++) {
                    int gk = k0 + akq;
                    int bytes = (K - gk)*4; bytes = bytes<0?0:(bytes>16?16:bytes);
                    const float* src = bytes ? (brp[p] + gk) : Bp;
                    cpa16(s2u(&Bs[(lrow + p*32)*ASTR + akq]), src, bytes);
                }
            } else {
#pragma unroll
                for (int p=0;p<4;p++) {
                    int k = bnk + p*8;
                    int ok = ((k0+k) < K) && ((n0+bn4) < N);
                    const float* src = ok ? (Bp + (long)(k0+k)*N + n0 + bn4) : Bp;
                    cpa16(s2u(&Bs[k*BSTR + bn4]), src, ok ? 16 : 0);
                }
            }
        } else {
            // synchronous fallback (odd K)
#pragma unroll
            for (int p=0;p<4;p++) {
                int gk = k0 + akq;
                uint4 u = {0u,0u,0u,0u};
                const float* ap = arp[p];
                if (gk+0 < K) u.x = __float_as_uint(ap[gk+0]);
                if (gk+1 < K) u.y = __float_as_uint(ap[gk+1]);
                if (gk+2 < K) u.z = __float_as_uint(ap[gk+2]);
                if (gk+3 < K) u.w = __float_as_uint(ap[gk+3]);
                *(uint4*)&As[(lrow + p*32)*ASTR + akq] = u;
            }
#pragma unroll
            for (int p=0;p<4;p++) {
                int k = bnk + p*8;
                uint4 u = {0u,0u,0u,0u};
                if ((k0+k) < K && (n0+bn4) < N) {
                    const float* bpr = Bp + (long)(k0+k)*N + n0 + bn4;
                    u.x = __float_as_uint(bpr[0]); u.y = __float_as_uint(bpr[1]);
                    u.z = __float_as_uint(bpr[2]); u.w = __float_as_uint(bpr[3]);
                }
                *(uint4*)&Bs[k*BSTR + bn4] = u;
            }
        }
    };

    auto compute = [&](const uint32_t* As, const uint32_t* Bs) {
#pragma unroll
        for (int ks=0;ks<4;ks++) {
            uint32_t a[4][4], b[4][2];
#pragma unroll
            for (int mt=0;mt<4;mt++) {
                int base = (wm + mt*16 + g)*ASTR + ks*8 + tig;
                a[mt][0] = As[base];
                a[mt][1] = As[base + 8*ASTR];
                a[mt][2] = As[base + 4];
                a[mt][3] = As[base + 8*ASTR + 4];
            }
#pragma unroll
            for (int nt=0;nt<4;nt++) {
                if (TRANSB) {
                    int base = (wn + nt*8 + g)*ASTR + ks*8 + tig;
                    b[nt][0] = Bs[base];
                    b[nt][1] = Bs[base + 4];
                } else {
                    int base = (ks*8 + tig)*BSTR + wn + nt*8 + g;
                    b[nt][0] = Bs[base];
                    b[nt][1] = Bs[base + 4*BSTR];
                }
            }
#pragma unroll
            for (int mt=0;mt<4;mt++)
#pragma unroll
                for (int nt=0;nt<4;nt++)
                    mma_tf32(c[mt][nt], a[mt], b[nt]);
        }
    };

    int ktn = (K+31)>>5;
    if (PIPE) {
        load_tile(AsB[0], BsB[0], 0);
        asm volatile("cp.async.commit_group;");
    }
    for (int kt=0; kt<ktn; kt++) {
        int cur = kt&1;
        if (PIPE) {
            if (kt+1 < ktn) load_tile(AsB[cur^1], BsB[cur^1], (kt+1)*32);
            asm volatile("cp.async.commit_group;");
            asm volatile("cp.async.wait_group 1;");
            __syncthreads();
            compute(AsB[cur], BsB[cur]);
        } else {
            load_tile(AsB[0], BsB[0], kt*32);
            __syncthreads();
            compute(AsB[0], BsB[0]);
        }
        __syncthreads();
    }

    // epilogue
#pragma unroll
    for (int mt=0;mt<4;mt++) {
        long m = m0 + wm + mt*16 + g;
#pragma unroll
        for (int nt=0;nt<4;nt++) {
            int n = n0 + wn + nt*8 + tig*2;
            if (n < N) {
                float bx=0.f, by=0.f;
                if (bp) { bx = bp[n]; by = bp[n+1]; }
                float* p0 = Cb + m*ldc + n;
                float* p1 = p0 + 8l*ldc;
                float2 v0, v1;
                v0.x = c[mt][nt][0]*scale + bx;
                v0.y = c[mt][nt][1]*scale + by;
                v1.x = c[mt][nt][2]*scale + bx;
                v1.y = c[mt][nt][3]*scale + by;
                if (ACC) {
                    float2 o0 = *(const float2*)p0, o1 = *(const float2*)p1;
                    v0.x+=o0.x; v0.y+=o0.y; v1.x+=o1.x; v1.y+=o1.y;
                }
                *(float2*)p0 = v0;
                *(float2*)p1 = v1;
            }
        }
    }
}

// ---------------------------------------------------------------------------
// warp-per-row softmax, 256 cols, 8 rows/block
__launch_bounds__(256)
__global__ void softmax_rows(float* __restrict__ sc)
{
    int warp = threadIdx.x>>5, lane = threadIdx.x&31;
    long row = (long)blockIdx.x*8 + warp;
    float* p = sc + row*256 + lane*8;
    float4 v0 = ((float4*)p)[0], v1 = ((float4*)p)[1];
    float m = fmaxf(fmaxf(fmaxf(v0.x,v0.y),fmaxf(v0.z,v0.w)),
                    fmaxf(fmaxf(v1.x,v1.y),fmaxf(v1.z,v1.w)));
#pragma unroll
    for (int o=16;o;o>>=1) m = fmaxf(m, __shfl_xor_sync(0xffffffffu, m, o));
    v0.x = expf(v0.x-m); v0.y = expf(v0.y-m); v0.z = expf(v0.z-m); v0.w = expf(v0.w-m);
    v1.x = expf(v1.x-m); v1.y = expf(v1.y-m); v1.z = expf(v1.z-m); v1.w = expf(v1.w-m);
    float s = v0.x+v0.y+v0.z+v0.w+v1.x+v1.y+v1.z+v1.w;
#pragma unroll
    for (int o=16;o;o>>=1) s += __shfl_xor_sync(0xffffffffu, s, o);
    float inv = 1.f/s;
    v0.x*=inv; v0.y*=inv; v0.z*=inv; v0.w*=inv;
    v1.x*=inv; v1.y*=inv; v1.z*=inv; v1.w*=inv;
    ((float4*)p)[0] = v0; ((float4*)p)[1] = v1;
}

// biGRU: grid 3*2*64 (m,d,b), 192 thr. Wh column register-resident.
__launch_bounds__(192)
__global__ void gru_rec(const float* __restrict__ xg_all, const float* __restrict__ Wh,
                        const float* __restrict__ bh, float* __restrict__ x_out,
                        float* __restrict__ tstep)
{
    int bx = blockIdx.x;
    int m = bx>>7, d = (bx>>6)&1, b = bx&63, md = m*2+d;
    int j = threadIdx.x;
    float wreg[64];
#pragma unroll
    for (int k=0;k<64;k++) wreg[k] = Wh[((long)md*64+k)*192 + j];
    float bhj = bh[md*192 + j];
    __shared__ alignas(16) float h_s[64];
    __shared__ float pre_s[192], xn_s[64];
    if (j<64) h_s[j]=0.f;
    const float* xg = xg_all + ((long)md*BS + (long)b*Ss)*192;
    for (int t=0;t<Ss;t++) {
        int s = d ? (Ss-1-t) : t;
        __syncthreads();
        float acc = bhj;
        const float4* h4p = (const float4*)h_s;
#pragma unroll
        for (int q=0;q<16;q++) {
            float4 h4 = h4p[q];
            acc += h4.x*wreg[4*q] + h4.y*wreg[4*q+1] + h4.z*wreg[4*q+2] + h4.w*wreg[4*q+3];
        }
        float xgv = xg[(long)s*192 + j];
        if (j<128) pre_s[j] = acc + xgv;
        else { pre_s[j] = acc; xn_s[j-128] = xgv; }
        __syncthreads();
        if (j<64) {
            float r = 1.f/(1.f+expf(-pre_s[j]));
            float zg = 1.f/(1.f+expf(-pre_s[64+j]));
            float n = tanhf(xn_s[j] + r*pre_s[128+j]);
            float hn = (1.f-zg)*n + zg*h_s[j];
            h_s[j] = hn;
            long row = (long)b*Ss + s;
            x_out[((long)m*BS + row)*128 + d*64 + j] = hn;
            tstep[row*384 + m*128 + d*64 + j] = hn;
        }
    }
}

// biLSTM: grid 2*64 (d,b), 512 thr.
__launch_bounds__(512, 1)
__global__ void lstm_rec(const float* __restrict__ xg_all, const float* __restrict__ Wh,
                         const float* __restrict__ bh, float* __restrict__ sf)
{
    extern __shared__ float sm[];
    float* Wlo = sm;
    float* h_s = sm + 64*512;
    float* pre_s = h_s + 128;
    int bx = blockIdx.x, d = bx>>6, b = bx&63;
    int j = threadIdx.x;
    const float* Whd = Wh + (long)d*128*512;
    float wreg[64];
#pragma unroll
    for (int k=0;k<64;k++) wreg[k] = Whd[(long)k*512 + j];
    for (int r=0;r<64;r++) Wlo[r*512 + j] = Whd[(long)(64+r)*512 + j];
    float bhj = bh[d*512 + j];
    float c = 0.f;
    if (j<128) h_s[j]=0.f;
    const float* xg = xg_all + ((long)d*BS + (long)b*Ss)*512;
    for (int t=0;t<Ss;t++) {
        int s = d ? (Ss-1-t) : t;
        __syncthreads();
        float acc = bhj;
        const float4* h4p = (const float4*)h_s;
#pragma unroll
        for (int q=0;q<16;q++) {
            float4 h4 = h4p[q];
            acc += h4.x*wreg[4*q] + h4.y*wreg[4*q+1] + h4.z*wreg[4*q+2] + h4.w*wreg[4*q+3];
        }
#pragma unroll
        for (int q=0;q<16;q++) {
            float4 h4 = h4p[16+q];
            acc += h4.x*Wlo[(4*q+0)*512+j] + h4.y*Wlo[(4*q+1)*512+j]
                 + h4.z*Wlo[(4*q+2)*512+j] + h4.w*Wlo[(4*q+3)*512+j];
        }
        acc += xg[(long)s*512 + j];
        pre_s[j] = acc;
        __syncthreads();
        if (j<128) {
            float ig = pre_s[j], fg = pre_s[128+j], gg = pre_s[256+j], og = pre_s[384+j];
            c = 1.f/(1.f+expf(-fg))*c + 1.f/(1.f+expf(-ig))*tanhf(gg);
            float h = 1.f/(1.f+expf(-og))*tanhf(c);
            h_s[j] = h;
            sf[((long)b*Ss + s)*256 + d*128 + j] = h;
        }
    }
}

// RGN: grid 2*64 (k,b), 384 thr.
__launch_bounds__(384, 1)
__global__ void rgn_rec(const float* __restrict__ xg_all, const float* __restrict__ Wh,
                        const float* __restrict__ state0, const float* __restrict__ state1,
                        float* __restrict__ outbuf)
{
    extern __shared__ float sm[];
    float* Wlo = sm;
    float* h_s = sm + 64*384;
    float* pre_s = h_s + 128;
    float* xn_s = pre_s + 384;
    int bx = blockIdx.x, kk = bx>>6, b = bx&63;
    int j = threadIdx.x;
    const float* Whd = Wh + (long)kk*128*384;
    float wreg[64];
#pragma unroll
    for (int k=0;k<64;k++) wreg[k] = Whd[(long)k*384 + j];
    for (int r=0;r<64;r++) Wlo[r*384 + j] = Whd[(long)(64+r)*384 + j];
    if (j<128) h_s[j] = (kk==0?state0:state1)[b*128 + j];
    const float* xg = xg_all + ((long)kk*BS + (long)b*Ss)*384;
    for (int t=0;t<Ss;t++) {
        int s = kk ? (Ss-1-t) : t;
        __syncthreads();
        float acc = 0.f;
        const float4* h4p = (const float4*)h_s;
#pragma unroll
        for (int q=0;q<16;q++) {
            float4 h4 = h4p[q];
            acc += h4.x*wreg[4*q] + h4.y*wreg[4*q+1] + h4.z*wreg[4*q+2] + h4.w*wreg[4*q+3];
        }
#pragma unroll
        for (int q=0;q<16;q++) {
            float4 h4 = h4p[16+q];
            acc += h4.x*Wlo[(4*q+0)*384+j] + h4.y*Wlo[(4*q+1)*384+j]
                 + h4.z*Wlo[(4*q+2)*384+j] + h4.w*Wlo[(4*q+3)*384+j];
        }
        float xgv = xg[(long)s*384 + j];
        if (j<256) pre_s[j] = acc + xgv;
        else { pre_s[j] = acc; xn_s[j-256] = xgv; }
        __syncthreads();
        if (j<128) {
            float r = 1.f/(1.f+expf(-pre_s[j]));
            float z = 1.f/(1.f+expf(-pre_s[128+j]));
            float n = tanhf(xn_s[j] + r*pre_s[256+j]);
            h_s[j] = (1.f-z)*n + z*h_s[j];
        }
    }
    __syncthreads();
    if (j<128) outbuf[((long)kk*64 + b)*128 + j] = h_s[j];
}

__launch_bounds__(32)
__global__ void final_fc(const float* __restrict__ outbuf,
                         const float* __restrict__ fc1W, const float* __restrict__ fc1b,
                         const float* __restrict__ fc2W, const float* __restrict__ fc2b,
                         float* __restrict__ out)
{
    int b = blockIdx.x, t = threadIdx.x;
    float acc = fc1b[t];
    for (int k=0;k<128;k++) {
        float x = outbuf[b*128+k] + outbuf[64*128 + b*128 + k];
        acc += x * fc1W[k*32 + t];
    }
    float h = acc > 0.f ? acc : 0.01f*acc;
    float v = h * fc2W[t];
#pragma unroll
    for (int o=16;o;o>>=1) v += __shfl_xor_sync(0xffffffffu, v, o);
    if (t==0) out[b] = v + fc2b[0];
}

extern "C" void kernel_launch(void* const* d_in, const int* in_sizes, int n_in,
                              void* d_out, int out_size)
{
    (void)in_sizes; (void)n_in; (void)out_size;
    const int*   sentences = (const int*)  d_in[0];
    const float* acoustic  = (const float*)d_in[1];
    const float* video     = (const float*)d_in[2];
    const float* state0    = (const float*)d_in[3];
    const float* state1    = (const float*)d_in[4];
    const float* emb       = (const float*)d_in[5];
    const float* proj_l_W  = (const float*)d_in[6];
    const float* proj_l_b  = (const float*)d_in[7];
    const float* proj_a_W  = (const float*)d_in[8];
    const float* proj_a_b  = (const float*)d_in[9];
    const float* proj_v_W  = (const float*)d_in[10];
    const float* proj_v_b  = (const float*)d_in[11];
    const float* gru_Wi    = (const float*)d_in[12];
    const float* gru_Wh    = (const float*)d_in[13];
    const float* gru_bi    = (const float*)d_in[14];
    const float* gru_bh    = (const float*)d_in[15];
    const float* lstm_Wi   = (const float*)d_in[16];
    const float* lstm_Wh   = (const float*)d_in[17];
    const float* lstm_bi   = (const float*)d_in[18];
    const float* lstm_bh   = (const float*)d_in[19];
    const float* rgn_Wx    = (const float*)d_in[20];
    const float* rgn_Wh    = (const float*)d_in[21];
    const float* rgn_b     = (const float*)d_in[22];
    const float* fc1_W     = (const float*)d_in[23];
    const float* fc1_b     = (const float*)d_in[24];
    const float* fc2_W     = (const float*)d_in[25];
    const float* fc2_b     = (const float*)d_in[26];
    float* out = (float*)d_out;

    float *seq,*xg_gru,*x,*tstep,*sc,*xg_lstm,*sf,*xg_rgn,*rgn_out;
    cudaGetSymbolAddress((void**)&seq, g_seq);
    cudaGetSymbolAddress((void**)&xg_gru, g_xg_gru);
    cudaGetSymbolAddress((void**)&x, g_x);
    cudaGetSymbolAddress((void**)&tstep, g_tstep);
    cudaGetSymbolAddress((void**)&sc, g_sc);
    cudaGetSymbolAddress((void**)&xg_lstm, g_xg_lstm);
    cudaGetSymbolAddress((void**)&sf, g_sf);
    cudaGetSymbolAddress((void**)&xg_rgn, g_xg_rgn);
    cudaGetSymbolAddress((void**)&rgn_out, g_rgn_out);

    const size_t shm = 4u*AWORDS*4u;   // 73728 B
    cudaFuncSetAttribute(gemm_tc<0,false,false,true,true>,  cudaFuncAttributeMaxDynamicSharedMemorySize, (int)shm);
    cudaFuncSetAttribute(gemm_tc<1,false,false,true,false>, cudaFuncAttributeMaxDynamicSharedMemorySize, (int)shm);
    cudaFuncSetAttribute(gemm_tc<2,true ,false,true,false>, cudaFuncAttributeMaxDynamicSharedMemorySize, (int)shm);
    cudaFuncSetAttribute(gemm_tc<3,false,true ,true,false>, cudaFuncAttributeMaxDynamicSharedMemorySize, (int)shm);
    cudaFuncSetAttribute(gemm_tc<0,false,false,true,false>, cudaFuncAttributeMaxDynamicSharedMemorySize, (int)shm);
    cudaFuncSetAttribute(lstm_rec, cudaFuncAttributeMaxDynamicSharedMemorySize, 134*1024);
    cudaFuncSetAttribute(rgn_rec,  cudaFuncAttributeMaxDynamicSharedMemorySize, 102*1024);

    // modality projections
    gemm_tc<0,false,false,true,true><<<dim3(1, BS/128, 1), 256, shm>>>(
        emb, proj_l_W, proj_l_b, seq, BS, 128, DL, 0,0,0,0, 128, 1.f, sentences, 0);
    gemm_tc<0,false,false,false,false><<<dim3(1, BS/128, 1), 256, 2u*AWORDS*4u>>>(
        acoustic, proj_a_W, proj_a_b, seq + 1l*BS*DH, BS, 128, DA, 0,0,0,0, 128, 1.f, nullptr, 0);
    gemm_tc<0,false,false,false,false><<<dim3(1, BS/128, 1), 256, 2u*AWORDS*4u>>>(
        video, proj_v_W, proj_v_b, seq + 2l*BS*DH, BS, 128, DV, 0,0,0,0, 128, 1.f, nullptr, 0);

    // GRU input projections — one batched launch (z = 6)
    gemm_tc<1,false,false,true,false><<<dim3(2, BS/128, 6), 256, shm>>>(
        seq, gru_Wi, gru_bi, xg_gru, BS, 192, 128,
        (long)BS*DH, 128l*192, 192, (long)BS*192, 192, 1.f, nullptr, 0);

    // biGRU recurrences (also initializes tstep slabs)
    gru_rec<<<3*2*64, 192>>>(xg_gru, gru_Wh, gru_bh, x, tstep);

    // JCAF: all 6 QK^T in one launch, one softmax, PV in two race-free groups
    const float scale = 0.08838834764831845f; // 1/sqrt(128)
    gemm_tc<2,true,false,true,false><<<dim3(2, 2, 384), 256, shm>>>(
        x, x, nullptr, sc, 256, 256, 128, 0,0,0,0, 256, scale, nullptr, 0);
    softmax_rows<<<6*Bb*Ss/8, 256>>>(sc);
    gemm_tc<3,false,true,true,false><<<dim3(1, 2, 192), 256, shm>>>(
        sc, x, nullptr, tstep, 256, 128, 256, 0,0,0,0, 384, 1.f, nullptr, 0);
    gemm_tc<3,false,true,true,false><<<dim3(1, 2, 192), 256, shm>>>(
        sc, x, nullptr, tstep, 256, 128, 256, 0,0,0,0, 384, 1.f, nullptr, 1);

    // LSTM input projections — batched (z = 2, shared A via sA = 0)
    gemm_tc<0,false,false,true,false><<<dim3(4, BS/128, 2), 256, shm>>>(
        tstep, lstm_Wi, lstm_bi, xg_lstm, BS, 512, 384,
        0, 384l*512, 512, (long)BS*512, 512, 1.f, nullptr, 0);

    // biLSTM recurrence
    lstm_rec<<<2*64, 512, 134*1024>>>(xg_lstm, lstm_Wh, lstm_bh, sf);

    // RGN input projections — batched (z = 2)
    gemm_tc<0,false,false,true,false><<<dim3(3, BS/128, 2), 256, shm>>>(
        sf, rgn_Wx, rgn_b, xg_rgn, BS, 384, 256,
        0, 256l*384, 384, (long)BS*384, 384, 1.f, nullptr, 0);

    // RGN recurrences
    rgn_rec<<<2*64, 384, 102*1024>>>(xg_rgn, rgn_Wh, state0, state1, rgn_out);

    // final FC
    final_fc<<<Bb, 32>>>(rgn_out, fc1_W, fc1_b, fc2_W, fc2_b, out);
}

// round 6
// speedup vs baseline: 1.9917x; 1.2514x over previous
#include <cuda_runtime.h>
#include <math.h>
#include <stdint.h>

#define Bb 64
#define Ss 256
#define BS (Bb*Ss)
#define DL 300
#define DA 74
#define DV 35
#define DH 128

__device__ float g_seq[3u*BS*DH];
__device__ float g_xg_gru[6u*BS*192];
__device__ float g_x[3u*BS*DH];
__device__ float g_tstep[(unsigned)BS*384];
__device__ float g_sc[6u*(unsigned)Bb*Ss*Ss];
__device__ float g_xg_lstm[2u*BS*512];
__device__ float g_sf[(unsigned)BS*256];
__device__ float g_xg_rgn[2u*BS*384];
__device__ float g_rgn_out[2u*Bb*128];

// ---------------------------------------------------------------------------
// helpers
// ---------------------------------------------------------------------------
typedef unsigned long long ull;

__device__ __forceinline__ uint32_t s2u(const void* p) {
    return (uint32_t)__cvta_generic_to_shared(p);
}
__device__ __forceinline__ void cpa16(uint32_t dst, const void* src, int bytes) {
    asm volatile("cp.async.cg.shared.global [%0], [%1], 16, %2;"
                 :: "r"(dst), "l"(src), "r"(bytes));
}
__device__ __forceinline__ void mma_tf32(float c[4], const uint32_t a[4], const uint32_t b[2]) {
    asm volatile(
        "mma.sync.aligned.m16n8k8.row.col.f32.tf32.tf32.f32 "
        "{%0,%1,%2,%3}, {%4,%5,%6,%7}, {%8,%9}, {%0,%1,%2,%3};"
        : "+f"(c[0]), "+f"(c[1]), "+f"(c[2]), "+f"(c[3])
        : "r"(a[0]), "r"(a[1]), "r"(a[2]), "r"(a[3]), "r"(b[0]), "r"(b[1]));
}
__device__ __forceinline__ ull pk(float x, float y) {
    ull r; asm("mov.b64 %0,{%1,%2};" : "=l"(r) : "f"(x), "f"(y)); return r;
}
__device__ __forceinline__ float2 upk(ull v) {
    float2 f; asm("mov.b64 {%0,%1},%2;" : "=f"(f.x), "=f"(f.y) : "l"(v)); return f;
}
__device__ __forceinline__ void ffma2(ull &d, ull a, ull b) {
    asm volatile("fma.rn.f32x2 %0, %1, %2, %0;" : "+l"(d) : "l"(a), "l"(b));
}
__device__ __forceinline__ void lds2x64(ull &a, ull &b, uint32_t addr) {
    asm volatile("ld.shared.v2.b64 {%0,%1},[%2];" : "=l"(a), "=l"(b) : "r"(addr));
}
__device__ __forceinline__ float sigf(float x) { return 1.f/(1.f + __expf(-x)); }
__device__ __forceinline__ float tanhfast(float x) {
    float y; asm("tanh.approx.f32 %0,%1;" : "=f"(y) : "f"(x)); return y;
}

// ---------------------------------------------------------------------------
// TF32 tensor-core GEMM, 3-stage cp.async pipeline, z-batched (modes as R4).
// ---------------------------------------------------------------------------
#define ASTR 36
#define BSTR 136
#define AWORDS (128*ASTR)          // 4608
#define STG_WORDS (2*AWORDS)       // 9216 per stage

template<int MODE, bool TRANSB, bool ACC, bool PIPE, bool GATHER>
__launch_bounds__(256, 2)
__global__ void gemm_tc(const float* __restrict__ A, const float* __restrict__ B,
                        const float* __restrict__ bias, float* __restrict__ C,
                        int M, int N, int K,
                        long sA, long sB, long sBias, long sC, int ldc,
                        float scale, const int* __restrict__ gidx, int aux)
{
    extern __shared__ uint32_t smp[];

    const int qtab[6]  = {0,0,1,1,2,2};
    const int kvtab[6] = {1,2,0,2,0,1};

    int z = blockIdx.z;
    const float *Ab, *Bp, *bp = nullptr;
    float* Cb;
    if (MODE == 0 || MODE == 1) {
        Ab = A + (MODE==1 ? (long)(z>>1)*sA : (long)z*sA);
        Bp = B + (long)z*sB;
        bp = bias ? bias + (long)z*sBias : nullptr;
        Cb = C + (long)z*sC;
    } else if (MODE == 2) {
        int p = z>>6, b = z&63;
        Ab = A + ((long)qtab[p]*BS + (long)b*Ss)*128;
        Bp = B + ((long)kvtab[p]*BS + (long)b*Ss)*128;
        Cb = C + (long)z*Ss*Ss;
    } else {
        int pp = z>>6, b = z&63;
        int p = 2*pp + aux;
        Ab = A + ((long)p*64 + b)*(long)Ss*Ss;
        Bp = B + ((long)kvtab[p]*BS + (long)b*Ss)*128;
        Cb = C + (long)qtab[p]*128 + (long)b*Ss*384;
    }

    int m0 = blockIdx.y*128, n0 = blockIdx.x*128;
    int tid = threadIdx.x;
    int warp = tid>>5, lane = tid&31;
    int g = lane>>2, tig = lane&3;
    int wm = (warp&1)*64, wn = (warp>>1)*32;

    float c[4][4][4];
#pragma unroll
    for (int mt=0;mt<4;mt++)
#pragma unroll
        for (int nt=0;nt<4;nt++)
#pragma unroll
            for (int i=0;i<4;i++) c[mt][nt][i]=0.f;

    int lrow = tid>>3;
    int akq  = (tid&7)*4;
    const float* arp[4];
#pragma unroll
    for (int p=0;p<4;p++) {
        long grow = m0 + lrow + p*32;
        long r = GATHER ? (long)gidx[grow] : grow;
        arp[p] = Ab + r*(long)K;
    }
    const float* brp[4];
    if (TRANSB) {
#pragma unroll
        for (int p=0;p<4;p++) brp[p] = Bp + (long)(n0 + lrow + p*32)*K;
    }
    int bnk = tid>>5;
    int bn4 = (tid&31)*4;

    auto load_tile = [&](int st, int k0) {
        uint32_t* As = smp + st*STG_WORDS;
        uint32_t* Bs = As + AWORDS;
        if (PIPE) {
#pragma unroll
            for (int p=0;p<4;p++) {
                int gk = k0 + akq;
                int bytes = (K - gk)*4; bytes = bytes<0?0:(bytes>16?16:bytes);
                const float* src = bytes ? (arp[p] + gk) : Ab;
                cpa16(s2u(&As[(lrow + p*32)*ASTR + akq]), src, bytes);
            }
            if (TRANSB) {
#pragma unroll
                for (int p=0;p<4;p++) {
                    int gk = k0 + akq;
                    int bytes = (K - gk)*4; bytes = bytes<0?0:(bytes>16?16:bytes);
                    const float* src = bytes ? (brp[p] + gk) : Bp;
                    cpa16(s2u(&Bs[(lrow + p*32)*ASTR + akq]), src, bytes);
                }
            } else {
#pragma unroll
                for (int p=0;p<4;p++) {
                    int k = bnk + p*8;
                    int ok = ((k0+k) < K) && ((n0+bn4) < N);
                    const float* src = ok ? (Bp + (long)(k0+k)*N + n0 + bn4) : Bp;
                    cpa16(s2u(&Bs[k*BSTR + bn4]), src, ok ? 16 : 0);
                }
            }
        } else {
#pragma unroll
            for (int p=0;p<4;p++) {
                int gk = k0 + akq;
                uint4 u = {0u,0u,0u,0u};
                const float* ap = arp[p];
                if (gk+0 < K) u.x = __float_as_uint(ap[gk+0]);
                if (gk+1 < K) u.y = __float_as_uint(ap[gk+1]);
                if (gk+2 < K) u.z = __float_as_uint(ap[gk+2]);
                if (gk+3 < K) u.w = __float_as_uint(ap[gk+3]);
                *(uint4*)&As[(lrow + p*32)*ASTR + akq] = u;
            }
#pragma unroll
            for (int p=0;p<4;p++) {
                int k = bnk + p*8;
                uint4 u = {0u,0u,0u,0u};
                if ((k0+k) < K && (n0+bn4) < N) {
                    const float* bpr = Bp + (long)(k0+k)*N + n0 + bn4;
                    u.x = __float_as_uint(bpr[0]); u.y = __float_as_uint(bpr[1]);
                    u.z = __float_as_uint(bpr[2]); u.w = __float_as_uint(bpr[3]);
                }
                *(uint4*)&Bs[k*BSTR + bn4] = u;
            }
        }
    };

    auto compute = [&](int st) {
        const uint32_t* As = smp + st*STG_WORDS;
        const uint32_t* Bs = As + AWORDS;
#pragma unroll
        for (int ks=0;ks<4;ks++) {
            uint32_t a[4][4], b[4][2];
#pragma unroll
            for (int mt=0;mt<4;mt++) {
                int base = (wm + mt*16 + g)*ASTR + ks*8 + tig;
                a[mt][0] = As[base];
                a[mt][1] = As[base + 8*ASTR];
                a[mt][2] = As[base + 4];
                a[mt][3] = As[base + 8*ASTR + 4];
            }
#pragma unroll
            for (int nt=0;nt<4;nt++) {
                if (TRANSB) {
                    int base = (wn + nt*8 + g)*ASTR + ks*8 + tig;
                    b[nt][0] = Bs[base];
                    b[nt][1] = Bs[base + 4];
                } else {
                    int base = (ks*8 + tig)*BSTR + wn + nt*8 + g;
                    b[nt][0] = Bs[base];
                    b[nt][1] = Bs[base + 4*BSTR];
                }
            }
#pragma unroll
            for (int mt=0;mt<4;mt++)
#pragma unroll
                for (int nt=0;nt<4;nt++)
                    mma_tf32(c[mt][nt], a[mt], b[nt]);
        }
    };

    int ktn = (K+31)>>5;
    if (PIPE) {
        load_tile(0, 0);
        asm volatile("cp.async.commit_group;");
        if (ktn > 1) load_tile(1, 32);
        asm volatile("cp.async.commit_group;");
        for (int kt=0; kt<ktn; kt++) {
            asm volatile("cp.async.wait_group 1;");
            __syncthreads();
            if (kt+2 < ktn) load_tile((kt+2)%3, (kt+2)*32);
            asm volatile("cp.async.commit_group;");
            compute(kt%3);
        }
    } else {
        for (int kt=0; kt<ktn; kt++) {
            load_tile(0, kt*32);
            __syncthreads();
            compute(0);
            __syncthreads();
        }
    }
    __syncthreads();

#pragma unroll
    for (int mt=0;mt<4;mt++) {
        long m = m0 + wm + mt*16 + g;
#pragma unroll
        for (int nt=0;nt<4;nt++) {
            int n = n0 + wn + nt*8 + tig*2;
            if (n < N) {
                float bx=0.f, by=0.f;
                if (bp) { bx = bp[n]; by = bp[n+1]; }
                float* p0 = Cb + m*ldc + n;
                float* p1 = p0 + 8l*ldc;
                float2 v0, v1;
                v0.x = c[mt][nt][0]*scale + bx;
                v0.y = c[mt][nt][1]*scale + by;
                v1.x = c[mt][nt][2]*scale + bx;
                v1.y = c[mt][nt][3]*scale + by;
                if (ACC) {
                    float2 o0 = *(const float2*)p0, o1 = *(const float2*)p1;
                    v0.x+=o0.x; v0.y+=o0.y; v1.x+=o1.x; v1.y+=o1.y;
                }
                *(float2*)p0 = v0;
                *(float2*)p1 = v1;
            }
        }
    }
}

// ---------------------------------------------------------------------------
__launch_bounds__(256)
__global__ void softmax_rows(float* __restrict__ sc)
{
    int warp = threadIdx.x>>5, lane = threadIdx.x&31;
    long row = (long)blockIdx.x*8 + warp;
    float* p = sc + row*256 + lane*8;
    float4 v0 = ((float4*)p)[0], v1 = ((float4*)p)[1];
    float m = fmaxf(fmaxf(fmaxf(v0.x,v0.y),fmaxf(v0.z,v0.w)),
                    fmaxf(fmaxf(v1.x,v1.y),fmaxf(v1.z,v1.w)));
#pragma unroll
    for (int o=16;o;o>>=1) m = fmaxf(m, __shfl_xor_sync(0xffffffffu, m, o));
    v0.x = __expf(v0.x-m); v0.y = __expf(v0.y-m); v0.z = __expf(v0.z-m); v0.w = __expf(v0.w-m);
    v1.x = __expf(v1.x-m); v1.y = __expf(v1.y-m); v1.z = __expf(v1.z-m); v1.w = __expf(v1.w-m);
    float s = v0.x+v0.y+v0.z+v0.w+v1.x+v1.y+v1.z+v1.w;
#pragma unroll
    for (int o=16;o;o>>=1) s += __shfl_xor_sync(0xffffffffu, s, o);
    float inv = 1.f/s;
    v0.x*=inv; v0.y*=inv; v0.z*=inv; v0.w*=inv;
    v1.x*=inv; v1.y*=inv; v1.z*=inv; v1.w*=inv;
    ((float4*)p)[0] = v0; ((float4*)p)[1] = v1;
}

// ---------------------------------------------------------------------------
// biGRU: grid 3*2*64, 192 thr; k-packed f32x2, all weights in regs.
// ---------------------------------------------------------------------------
__launch_bounds__(192, 3)
__global__ void gru_rec(const float* __restrict__ xg_all, const float* __restrict__ Wh,
                        const float* __restrict__ bh, float* __restrict__ x_out,
                        float* __restrict__ tstep)
{
    int bx = blockIdx.x;
    int m = bx>>7, d = (bx>>6)&1, b = bx&63, md = m*2+d;
    int j = threadIdx.x;
    ull w2[32];
#pragma unroll
    for (int q=0;q<32;q++)
        w2[q] = pk(Wh[((long)md*64 + 2*q)*192 + j], Wh[((long)md*64 + 2*q+1)*192 + j]);
    float bhj = bh[md*192 + j];
    __shared__ alignas(16) float h_s[64];
    __shared__ float pre_s[192], xn_s[64];
    uint32_t hsa = s2u(h_s);
    if (j<64) h_s[j]=0.f;
    const float* xg = xg_all + ((long)md*BS + (long)b*Ss)*192;
    for (int t=0;t<Ss;t++) {
        int s = d ? (Ss-1-t) : t;
        __syncthreads();
        ull acc2 = pk(bhj, 0.f);
#pragma unroll
        for (int q=0;q<16;q++) {
            ull h0,h1; lds2x64(h0,h1, hsa + q*16);
            ffma2(acc2, h0, w2[2*q]);
            ffma2(acc2, h1, w2[2*q+1]);
        }
        float2 ac = upk(acc2);
        float acc = ac.x + ac.y;
        float xgv = xg[(long)s*192 + j];
        if (j<128) pre_s[j] = acc + xgv;
        else { pre_s[j] = acc; xn_s[j-128] = xgv; }
        __syncthreads();
        if (j<64) {
            float r = sigf(pre_s[j]);
            float zg = sigf(pre_s[64+j]);
            float n = tanhfast(xn_s[j] + r*pre_s[128+j]);
            float hn = (1.f-zg)*n + zg*h_s[j];
            h_s[j] = hn;
            long row = (long)b*Ss + s;
            x_out[((long)m*BS + row)*128 + d*64 + j] = hn;
            tstep[row*384 + m*128 + d*64 + j] = hn;
        }
    }
}

// ---------------------------------------------------------------------------
// biLSTM: grid 2*64, 512 thr; k-packed f32x2, k<96 regs + k>=96 smem.
// ---------------------------------------------------------------------------
__launch_bounds__(512, 1)
__global__ void lstm_rec(const float* __restrict__ xg_all, const float* __restrict__ Wh,
                         const float* __restrict__ bh, float* __restrict__ sf)
{
    extern __shared__ unsigned char smraw[];
    ull*   Wlo2  = (ull*)smraw;                         // [16][512]
    float* h_s   = (float*)(smraw + 16*512*8);          // 128 (16B aligned)
    float* pre_s = (float*)(smraw + 16*512*8 + 512);    // 512
    int bx = blockIdx.x, d = bx>>6, b = bx&63;
    int j = threadIdx.x;
    const float* Whd = Wh + (long)d*128*512;
    ull w2[48];
#pragma unroll
    for (int q=0;q<48;q++)
        w2[q] = pk(Whd[(long)(2*q)*512 + j], Whd[(long)(2*q+1)*512 + j]);
    for (int q=0;q<16;q++)
        Wlo2[q*512 + j] = pk(Whd[(long)(96+2*q)*512 + j], Whd[(long)(97+2*q)*512 + j]);
    float bhj = bh[d*512 + j];
    float c = 0.f;
    if (j<128) h_s[j]=0.f;
    uint32_t hsa = s2u(h_s);
    const float* xg = xg_all + ((long)d*BS + (long)b*Ss)*512;
    for (int t=0;t<Ss;t++) {
        int s = d ? (Ss-1-t) : t;
        __syncthreads();
        ull acc2 = pk(bhj, 0.f);
#pragma unroll
        for (int q=0;q<24;q++) {
            ull h0,h1; lds2x64(h0,h1, hsa + q*16);
            ffma2(acc2, h0, w2[2*q]);
            ffma2(acc2, h1, w2[2*q+1]);
        }
#pragma unroll
        for (int q=0;q<8;q++) {
            ull h0,h1; lds2x64(h0,h1, hsa + 384 + q*16);
            ffma2(acc2, h0, Wlo2[(2*q)*512 + j]);
            ffma2(acc2, h1, Wlo2[(2*q+1)*512 + j]);
        }
        float2 ac = upk(acc2);
        float acc = ac.x + ac.y + xg[(long)s*512 + j];
        pre_s[j] = acc;
        __syncthreads();
        if (j<128) {
            float ig = pre_s[j], fg = pre_s[128+j], gg = pre_s[256+j], og = pre_s[384+j];
            c = sigf(fg)*c + sigf(ig)*tanhfast(gg);
            float h = sigf(og)*tanhfast(c);
            h_s[j] = h;
            sf[((long)b*Ss + s)*256 + d*128 + j] = h;
        }
    }
}

// ---------------------------------------------------------------------------
// RGN: grid 2*64, 384 thr; k-packed f32x2, ALL 128 k in regs.
// ---------------------------------------------------------------------------
__launch_bounds__(384, 1)
__global__ void rgn_rec(const float* __restrict__ xg_all, const float* __restrict__ Wh,
                        const float* __restrict__ state0, const float* __restrict__ state1,
                        float* __restrict__ outbuf)
{
    __shared__ alignas(16) float h_s[128];
    __shared__ float pre_s[384], xn_s[128];
    int bx = blockIdx.x, kk = bx>>6, b = bx&63;
    int j = threadIdx.x;
    const float* Whd = Wh + (long)kk*128*384;
    ull w2[64];
#pragma unroll
    for (int q=0;q<64;q++)
        w2[q] = pk(Whd[(long)(2*q)*384 + j], Whd[(long)(2*q+1)*384 + j]);
    if (j<128) h_s[j] = (kk==0?state0:state1)[b*128 + j];
    uint32_t hsa = s2u(h_s);
    const float* xg = xg_all + ((long)kk*BS + (long)b*Ss)*384;
    for (int t=0;t<Ss;t++) {
        int s = kk ? (Ss-1-t) : t;
        __syncthreads();
        ull acc2 = pk(0.f, 0.f);
#pragma unroll
        for (int q=0;q<32;q++) {
            ull h0,h1; lds2x64(h0,h1, hsa + q*16);
            ffma2(acc2, h0, w2[2*q]);
            ffma2(acc2, h1, w2[2*q+1]);
        }
        float2 ac = upk(acc2);
        float acc = ac.x + ac.y;
        float xgv = xg[(long)s*384 + j];
        if (j<256) pre_s[j] = acc + xgv;
        else { pre_s[j] = acc; xn_s[j-256] = xgv; }
        __syncthreads();
        if (j<128) {
            float r = sigf(pre_s[j]);
            float z = sigf(pre_s[128+j]);
            float n = tanhfast(xn_s[j] + r*pre_s[256+j]);
            h_s[j] = (1.f-z)*n + z*h_s[j];
        }
    }
    __syncthreads();
    if (j<128) outbuf[((long)kk*64 + b)*128 + j] = h_s[j];
}

__launch_bounds__(32)
__global__ void final_fc(const float* __restrict__ outbuf,
                         const float* __restrict__ fc1W, const float* __restrict__ fc1b,
                         const float* __restrict__ fc2W, const float* __restrict__ fc2b,
                         float* __restrict__ out)
{
    int b = blockIdx.x, t = threadIdx.x;
    float acc = fc1b[t];
    for (int k=0;k<128;k++) {
        float x = outbuf[b*128+k] + outbuf[64*128 + b*128 + k];
        acc += x * fc1W[k*32 + t];
    }
    float h = acc > 0.f ? acc : 0.01f*acc;
    float v = h * fc2W[t];
#pragma unroll
    for (int o=16;o;o>>=1) v += __shfl_xor_sync(0xffffffffu, v, o);
    if (t==0) out[b] = v + fc2b[0];
}

extern "C" void kernel_launch(void* const* d_in, const int* in_sizes, int n_in,
                              void* d_out, int out_size)
{
    (void)in_sizes; (void)n_in; (void)out_size;
    const int*   sentences = (const int*)  d_in[0];
    const float* acoustic  = (const float*)d_in[1];
    const float* video     = (const float*)d_in[2];
    const float* state0    = (const float*)d_in[3];
    const float* state1    = (const float*)d_in[4];
    const float* emb       = (const float*)d_in[5];
    const float* proj_l_W  = (const float*)d_in[6];
    const float* proj_l_b  = (const float*)d_in[7];
    const float* proj_a_W  = (const float*)d_in[8];
    const float* proj_a_b  = (const float*)d_in[9];
    const float* proj_v_W  = (const float*)d_in[10];
    const float* proj_v_b  = (const float*)d_in[11];
    const float* gru_Wi    = (const float*)d_in[12];
    const float* gru_Wh    = (const float*)d_in[13];
    const float* gru_bi    = (const float*)d_in[14];
    const float* gru_bh    = (const float*)d_in[15];
    const float* lstm_Wi   = (const float*)d_in[16];
    const float* lstm_Wh   = (const float*)d_in[17];
    const float* lstm_bi   = (const float*)d_in[18];
    const float* lstm_bh   = (const float*)d_in[19];
    const float* rgn_Wx    = (const float*)d_in[20];
    const float* rgn_Wh    = (const float*)d_in[21];
    const float* rgn_b     = (const float*)d_in[22];
    const float* fc1_W     = (const float*)d_in[23];
    const float* fc1_b     = (const float*)d_in[24];
    const float* fc2_W     = (const float*)d_in[25];
    const float* fc2_b     = (const float*)d_in[26];
    float* out = (float*)d_out;

    float *seq,*xg_gru,*x,*tstep,*sc,*xg_lstm,*sf,*xg_rgn,*rgn_out;
    cudaGetSymbolAddress((void**)&seq, g_seq);
    cudaGetSymbolAddress((void**)&xg_gru, g_xg_gru);
    cudaGetSymbolAddress((void**)&x, g_x);
    cudaGetSymbolAddress((void**)&tstep, g_tstep);
    cudaGetSymbolAddress((void**)&sc, g_sc);
    cudaGetSymbolAddress((void**)&xg_lstm, g_xg_lstm);
    cudaGetSymbolAddress((void**)&sf, g_sf);
    cudaGetSymbolAddress((void**)&xg_rgn, g_xg_rgn);
    cudaGetSymbolAddress((void**)&rgn_out, g_rgn_out);

    const size_t shm3 = 3u*STG_WORDS*4u;   // 110592 B
    const size_t shm1 = 1u*STG_WORDS*4u;   // 36864 B (sync path)
    cudaFuncSetAttribute(gemm_tc<0,false,false,true,true>,   cudaFuncAttributeMaxDynamicSharedMemorySize, (int)shm3);
    cudaFuncSetAttribute(gemm_tc<0,false,false,true,false>,  cudaFuncAttributeMaxDynamicSharedMemorySize, (int)shm3);
    cudaFuncSetAttribute(gemm_tc<0,false,false,false,false>, cudaFuncAttributeMaxDynamicSharedMemorySize, (int)shm1);
    cudaFuncSetAttribute(gemm_tc<1,false,false,true,false>,  cudaFuncAttributeMaxDynamicSharedMemorySize, (int)shm3);
    cudaFuncSetAttribute(gemm_tc<2,true ,false,true,false>,  cudaFuncAttributeMaxDynamicSharedMemorySize, (int)shm3);
    cudaFuncSetAttribute(gemm_tc<3,false,true ,true,false>,  cudaFuncAttributeMaxDynamicSharedMemorySize, (int)shm3);
    cudaFuncSetAttribute(lstm_rec, cudaFuncAttributeMaxDynamicSharedMemorySize, 72*1024);

    // modality projections
    gemm_tc<0,false,false,true,true><<<dim3(1, BS/128, 1), 256, shm3>>>(
        emb, proj_l_W, proj_l_b, seq, BS, 128, DL, 0,0,0,0, 128, 1.f, sentences, 0);
    gemm_tc<0,false,false,false,false><<<dim3(1, BS/128, 1), 256, shm1>>>(
        acoustic, proj_a_W, proj_a_b, seq + 1l*BS*DH, BS, 128, DA, 0,0,0,0, 128, 1.f, nullptr, 0);
    gemm_tc<0,false,false,false,false><<<dim3(1, BS/128, 1), 256, shm1>>>(
        video, proj_v_W, proj_v_b, seq + 2l*BS*DH, BS, 128, DV, 0,0,0,0, 128, 1.f, nullptr, 0);

    // GRU input projections (batched z=6)
    gemm_tc<1,false,false,true,false><<<dim3(2, BS/128, 6), 256, shm3>>>(
        seq, gru_Wi, gru_bi, xg_gru, BS, 192, 128,
        (long)BS*DH, 128l*192, 192, (long)BS*192, 192, 1.f, nullptr, 0);

    gru_rec<<<3*2*64, 192>>>(xg_gru, gru_Wh, gru_bh, x, tstep);

    // JCAF
    const float scale = 0.08838834764831845f;
    gemm_tc<2,true,false,true,false><<<dim3(2, 2, 384), 256, shm3>>>(
        x, x, nullptr, sc, 256, 256, 128, 0,0,0,0, 256, scale, nullptr, 0);
    softmax_rows<<<6*Bb*Ss/8, 256>>>(sc);
    gemm_tc<3,false,true,true,false><<<dim3(1, 2, 192), 256, shm3>>>(
        sc, x, nullptr, tstep, 256, 128, 256, 0,0,0,0, 384, 1.f, nullptr, 0);
    gemm_tc<3,false,true,true,false><<<dim3(1, 2, 192), 256, shm3>>>(
        sc, x, nullptr, tstep, 256, 128, 256, 0,0,0,0, 384, 1.f, nullptr, 1);

    // LSTM input projections (batched z=2)
    gemm_tc<0,false,false,true,false><<<dim3(4, BS/128, 2), 256, shm3>>>(
        tstep, lstm_Wi, lstm_bi, xg_lstm, BS, 512, 384,
        0, 384l*512, 512, (long)BS*512, 512, 1.f, nullptr, 0);

    lstm_rec<<<2*64, 512, 16*512*8 + 512 + 2048>>>(xg_lstm, lstm_Wh, lstm_bh, sf);

    // RGN input projections (batched z=2)
    gemm_tc<0,false,false,true,false><<<dim3(3, BS/128, 2), 256, shm3>>>(
        sf, rgn_Wx, rgn_b, xg_rgn, BS, 384, 256,
        0, 256l*384, 384, (long)BS*384, 384, 1.f, nullptr, 0);

    rgn_rec<<<2*64, 384>>>(xg_rgn, rgn_Wh, state0, state1, rgn_out);

    final_fc<<<Bb, 32>>>(rgn_out, fc1_W, fc1_b, fc2_W, fc2_b, out);
}